// round 2
// baseline (speedup 1.0000x reference)
#include <cuda_runtime.h>
#include <cstdint>
#include <cstddef>

// Problem constants
#define N_NODES 50000
#define NP      50048          // padded to 782*64 = 391*128
#define D       128
#define BN_EPS  1e-5f

// ---------------- scratch (static device globals; no runtime alloc) -------------
__device__ float g_x  [(size_t)NP * D];      // padded copy of x
__device__ float g_m  [(size_t)NP * D];      // per-node message precompute x@W_msg+b
__device__ float g_as [NP];                  // x . W_att[:d]
__device__ float g_ad [NP];                  // x . W_att[d:]
__device__ float g_agg[(size_t)NP * D];      // scatter-add target
__device__ float g_g  [(size_t)NP * 768];    // [gi(384) | gh(384)] per node
__device__ float g_h  [(size_t)NP * D];      // h_new before BN
__device__ float g_sum[D];
__device__ float g_ssq[D];
__device__ int   g_is64;                     // edge_index dtype flag

__device__ __forceinline__ float sigm(float v) { return 1.f / (1.f + __expf(-v)); }

// =================================================================================
// Kernel 0: detect edge_index dtype (int32 vs int64). JAX without x64 silently
// emits int32 even though the reference asks for int64. Interpreting the first
// 64 entries as int64: random int32 pairs (lo,hi) give lo + hi*2^32 which is
// >= N_NODES unless hi==0 (prob ~2e-5 per entry) -> unambiguous discriminator.
// =================================================================================
__global__ void detect_kernel(const void* ei_raw, int E)
{
    const long long* e64 = (const long long*)ei_raw;
    int n = E < 64 ? E : 64;
    int ok = 1;
    for (int i = 0; i < n; i++) {
        long long v = e64[i];
        if (v < 0 || v >= N_NODES) { ok = 0; break; }
    }
    g_is64 = ok;
}

// =================================================================================
// Kernel A: per-node precompute.
//  - copy x into padded g_x (zeros beyond N)
//  - m = x @ W_msg + b_msg         (64-node tile per block, 256 threads, 4x8 frags)
//  - a_s = x . W_att[:128], a_d = x . W_att[128:]
//  - zero g_agg for this node range; block 0 zeros BN accumulators
// =================================================================================
__global__ __launch_bounds__(256) void node_pre_kernel(
    const float* __restrict__ x, const float* __restrict__ W_msg,
    const float* __restrict__ b_msg, const float* __restrict__ W_att)
{
    __shared__ __align__(16) float xs[64][132];   // node-major x tile (padded stride)
    __shared__ __align__(16) float Wc[16][128];   // W_msg k-chunk
    __shared__ float Was[128], Wad[128];

    const int tid = threadIdx.x;
    const int n0  = blockIdx.x * 64;

    if (tid < 128) { Was[tid] = W_att[tid]; Wad[tid] = W_att[128 + tid]; }

    // load x tile (guard rows >= N with zeros), also write padded g_x
    for (int i = tid; i < 64 * 32; i += 256) {
        int node = i >> 5, cq = i & 31;
        float4 v = make_float4(0.f, 0.f, 0.f, 0.f);
        int gn = n0 + node;
        if (gn < N_NODES) v = *(const float4*)&x[(size_t)gn * D + cq * 4];
        *(float4*)&xs[node][cq * 4] = v;
        *(float4*)&g_x[(size_t)gn * D + cq * 4] = v;
    }
    // zero agg for this range
    for (int i = tid; i < 64 * 32; i += 256)
        *(float4*)&g_agg[(size_t)n0 * D + i * 4] = make_float4(0.f, 0.f, 0.f, 0.f);
    if (blockIdx.x == 0 && tid < 128) { g_sum[tid] = 0.f; g_ssq[tid] = 0.f; }

    const int tr = tid >> 4;          // 0..15 -> 4 nodes each
    const int tc = tid & 15;          // 0..15 -> 8 cols each
    const int nt = tr * 4, c0 = tc * 8;
    float acc[4][8];
#pragma unroll
    for (int i = 0; i < 4; i++)
#pragma unroll
        for (int j = 0; j < 8; j++) acc[i][j] = 0.f;

    for (int kc = 0; kc < 8; kc++) {
        __syncthreads();
        for (int i = tid; i < 512; i += 256) {   // 16x128 floats as float4
            int kk = i >> 5, cq = i & 31;
            *(float4*)&Wc[kk][cq * 4] =
                *(const float4*)&W_msg[(size_t)(kc * 16 + kk) * D + cq * 4];
        }
        __syncthreads();
#pragma unroll
        for (int kk = 0; kk < 16; kk++) {
            int k = kc * 16 + kk;
            float xv0 = xs[nt + 0][k], xv1 = xs[nt + 1][k];
            float xv2 = xs[nt + 2][k], xv3 = xs[nt + 3][k];
            float4 w0 = *(const float4*)&Wc[kk][c0];
            float4 w1 = *(const float4*)&Wc[kk][c0 + 4];
            float wv[8] = {w0.x, w0.y, w0.z, w0.w, w1.x, w1.y, w1.z, w1.w};
#pragma unroll
            for (int j = 0; j < 8; j++) {
                acc[0][j] += xv0 * wv[j]; acc[1][j] += xv1 * wv[j];
                acc[2][j] += xv2 * wv[j]; acc[3][j] += xv3 * wv[j];
            }
        }
    }

    float bm[8];
#pragma unroll
    for (int j = 0; j < 8; j++) bm[j] = b_msg[c0 + j];
#pragma unroll
    for (int i = 0; i < 4; i++) {
        int n = n0 + nt + i;   // always < NP (padded writes OK)
        float4 v0 = make_float4(acc[i][0] + bm[0], acc[i][1] + bm[1],
                                acc[i][2] + bm[2], acc[i][3] + bm[3]);
        float4 v1 = make_float4(acc[i][4] + bm[4], acc[i][5] + bm[5],
                                acc[i][6] + bm[6], acc[i][7] + bm[7]);
        *(float4*)&g_m[(size_t)n * D + c0]     = v0;
        *(float4*)&g_m[(size_t)n * D + c0 + 4] = v1;
    }

    // attention pre-dots: 64 nodes x 2
    if (tid < 128) {
        int node = tid >> 1, sel = tid & 1;
        const float* wv = sel ? Wad : Was;
        float a0 = 0.f, a1 = 0.f, a2 = 0.f, a3 = 0.f;
#pragma unroll 8
        for (int k = 0; k < 128; k += 4) {
            a0 += xs[node][k]     * wv[k];
            a1 += xs[node][k + 1] * wv[k + 1];
            a2 += xs[node][k + 2] * wv[k + 2];
            a3 += xs[node][k + 3] * wv[k + 3];
        }
        float r = (a0 + a1) + (a2 + a3);
        if (sel) g_ad[n0 + node] = r; else g_as[n0 + node] = r;
    }
}

// =================================================================================
// Kernel B: edge pass. One warp per edge:
//   att = sigmoid(a_s[src] + a_d[dst] + b_att)
//   agg[dst] += m[src] * att      (32 lanes x red.global.add.v4.f32)
// Indices range-guarded: bad indices skip instead of trapping.
// =================================================================================
__global__ __launch_bounds__(256) void edge_kernel(
    const void* __restrict__ ei_raw, const float* __restrict__ b_att, int E)
{
    int gw   = (blockIdx.x * blockDim.x + threadIdx.x) >> 5;
    int lane = threadIdx.x & 31;
    if (gw >= E) return;

    int src, dst;
    if (g_is64) {
        const long long* e = (const long long*)ei_raw;
        src = (int)e[gw];
        dst = (int)e[(size_t)E + gw];
    } else {
        const int* e = (const int*)ei_raw;
        src = e[gw];
        dst = e[E + gw];
    }
    if ((unsigned)src >= N_NODES || (unsigned)dst >= N_NODES) return;

    float att = sigm(g_as[src] + g_ad[dst] + b_att[0]);

    float4 v = *(const float4*)&g_m[(size_t)src * D + lane * 4];
    float* o = &g_agg[(size_t)dst * D + lane * 4];
    asm volatile("red.global.add.v4.f32 [%0], {%1, %2, %3, %4};"
                 :: "l"(o), "f"(v.x * att), "f"(v.y * att),
                    "f"(v.z * att), "f"(v.w * att)
                 : "memory");
}

// =================================================================================
// Kernel C: GEMM  g_g[NP, 768] where cols [0,384)=agg@W_ih^T, [384,768)=x@W_hh^T.
// blockIdx.x in 0..5 selects 128-col tile (halves pick A operand & W matrix),
// blockIdx.y in 0..390 selects 128-node tile. 256 thr, 8x8 register frags,
// k-chunks of 16, A stored k-major in smem.
// =================================================================================
__global__ __launch_bounds__(256) void gemm_kernel(
    const float* __restrict__ W_ih, const float* __restrict__ W_hh,
    const float* __restrict__ b_ih, const float* __restrict__ b_hh)
{
    __shared__ __align__(16) float As[16][132];
    __shared__ __align__(16) float Bs[16][132];

    const int bx = blockIdx.x, tid = threadIdx.x;
    const int n0 = blockIdx.y * 128;
    const bool ih = (bx < 3);
    const float* A = ih ? g_agg : g_x;
    const float* W = ih ? W_ih : W_hh;
    const float* bptr = ih ? b_ih : b_hh;
    const int wro = (ih ? bx : bx - 3) * 128;

    const int tr = tid >> 4, tc = tid & 15;
    float acc[8][8];
#pragma unroll
    for (int i = 0; i < 8; i++)
#pragma unroll
        for (int j = 0; j < 8; j++) acc[i][j] = 0.f;

    for (int kc = 0; kc < 8; kc++) {
        int k0 = kc * 16;
        __syncthreads();
        for (int i = tid; i < 512; i += 256) {     // A: 128 nodes x 16 k
            int node = i >> 2, kq = i & 3;
            float4 v = *(const float4*)&A[(size_t)(n0 + node) * D + k0 + kq * 4];
            As[kq * 4 + 0][node] = v.x; As[kq * 4 + 1][node] = v.y;
            As[kq * 4 + 2][node] = v.z; As[kq * 4 + 3][node] = v.w;
        }
        for (int i = tid; i < 512; i += 256) {     // B: 128 out-rows x 16 k (transpose)
            int oo = i >> 2, kq = i & 3;
            float4 v = *(const float4*)&W[(size_t)(wro + oo) * D + k0 + kq * 4];
            Bs[kq * 4 + 0][oo] = v.x; Bs[kq * 4 + 1][oo] = v.y;
            Bs[kq * 4 + 2][oo] = v.z; Bs[kq * 4 + 3][oo] = v.w;
        }
        __syncthreads();
#pragma unroll
        for (int kk = 0; kk < 16; kk++) {
            float4 a0 = *(const float4*)&As[kk][tr * 8];
            float4 a1 = *(const float4*)&As[kk][tr * 8 + 4];
            float4 b0 = *(const float4*)&Bs[kk][tc * 8];
            float4 b1 = *(const float4*)&Bs[kk][tc * 8 + 4];
            float a[8] = {a0.x, a0.y, a0.z, a0.w, a1.x, a1.y, a1.z, a1.w};
            float b[8] = {b0.x, b0.y, b0.z, b0.w, b1.x, b1.y, b1.z, b1.w};
#pragma unroll
            for (int i = 0; i < 8; i++)
#pragma unroll
                for (int j = 0; j < 8; j++) acc[i][j] += a[i] * b[j];
        }
    }

    float bias[8];
#pragma unroll
    for (int j = 0; j < 8; j++) bias[j] = bptr[wro + tc * 8 + j];
#pragma unroll
    for (int i = 0; i < 8; i++) {
        int n = n0 + tr * 8 + i;
        size_t base = (size_t)n * 768 + bx * 128 + tc * 8;
        float4 v0 = make_float4(acc[i][0] + bias[0], acc[i][1] + bias[1],
                                acc[i][2] + bias[2], acc[i][3] + bias[3]);
        float4 v1 = make_float4(acc[i][4] + bias[4], acc[i][5] + bias[5],
                                acc[i][6] + bias[6], acc[i][7] + bias[7]);
        *(float4*)&g_g[base]     = v0;
        *(float4*)&g_g[base + 4] = v1;
    }
}

// =================================================================================
// Kernel D: GRU elementwise + BN column-stat accumulation.
// Block = 128 nodes (16 iters of 8 rows x 32 col-groups), 256 threads.
// =================================================================================
__global__ __launch_bounds__(256) void gru_kernel(const float* __restrict__ x)
{
    __shared__ float rs_[8][128];
    __shared__ float rq_[8][128];

    const int tid = threadIdx.x;
    const int c4 = tid & 31;       // float4 col group
    const int rs = tid >> 5;       // 0..7
    float4 s = make_float4(0.f, 0.f, 0.f, 0.f);
    float4 q = make_float4(0.f, 0.f, 0.f, 0.f);

    for (int it = 0; it < 16; it++) {
        int n = blockIdx.x * 128 + it * 8 + rs;
        if (n >= N_NODES) break;
        size_t gb = (size_t)n * 768 + c4 * 4;
        float4 ir = *(const float4*)&g_g[gb];
        float4 iz = *(const float4*)&g_g[gb + 128];
        float4 in_ = *(const float4*)&g_g[gb + 256];
        float4 hr = *(const float4*)&g_g[gb + 384];
        float4 hz = *(const float4*)&g_g[gb + 512];
        float4 hn = *(const float4*)&g_g[gb + 640];
        float4 xv = *(const float4*)&x[(size_t)n * D + c4 * 4];

        float4 h;
        {
            float r = sigm(ir.x + hr.x), z = sigm(iz.x + hz.x);
            float nn = tanhf(in_.x + r * hn.x); h.x = (1.f - z) * nn + z * xv.x;
        }
        {
            float r = sigm(ir.y + hr.y), z = sigm(iz.y + hz.y);
            float nn = tanhf(in_.y + r * hn.y); h.y = (1.f - z) * nn + z * xv.y;
        }
        {
            float r = sigm(ir.z + hr.z), z = sigm(iz.z + hz.z);
            float nn = tanhf(in_.z + r * hn.z); h.z = (1.f - z) * nn + z * xv.z;
        }
        {
            float r = sigm(ir.w + hr.w), z = sigm(iz.w + hz.w);
            float nn = tanhf(in_.w + r * hn.w); h.w = (1.f - z) * nn + z * xv.w;
        }
        *(float4*)&g_h[(size_t)n * D + c4 * 4] = h;
        s.x += h.x; s.y += h.y; s.z += h.z; s.w += h.w;
        q.x += h.x * h.x; q.y += h.y * h.y; q.z += h.z * h.z; q.w += h.w * h.w;
    }

    *(float4*)&rs_[rs][c4 * 4] = s;
    *(float4*)&rq_[rs][c4 * 4] = q;
    __syncthreads();
    if (tid < 128) {
        float a = 0.f, b = 0.f;
#pragma unroll
        for (int r = 0; r < 8; r++) { a += rs_[r][tid]; b += rq_[r][tid]; }
        atomicAdd(&g_sum[tid], a);
        atomicAdd(&g_ssq[tid], b);
    }
}

// =================================================================================
// Kernel E: BatchNorm normalize (training-mode batch stats, biased var).
// =================================================================================
__global__ __launch_bounds__(256) void bn_kernel(
    const float* __restrict__ gamma, const float* __restrict__ beta,
    float* __restrict__ out)
{
    int idx = blockIdx.x * 256 + threadIdx.x;     // float4 index
    if (idx >= N_NODES * 32) return;
    int c4 = idx & 31;
    const float inv_n = 1.f / (float)N_NODES;

    float4 h  = *(const float4*)&g_h[(size_t)idx * 4];
    float4 sm = *(const float4*)&g_sum[c4 * 4];
    float4 sq = *(const float4*)&g_ssq[c4 * 4];
    float4 ga = *(const float4*)&gamma[c4 * 4];
    float4 be = *(const float4*)&beta[c4 * 4];

    float4 o;
    {
        float mean = sm.x * inv_n; float var = sq.x * inv_n - mean * mean;
        o.x = ga.x * (h.x - mean) * rsqrtf(var + BN_EPS) + be.x;
    }
    {
        float mean = sm.y * inv_n; float var = sq.y * inv_n - mean * mean;
        o.y = ga.y * (h.y - mean) * rsqrtf(var + BN_EPS) + be.y;
    }
    {
        float mean = sm.z * inv_n; float var = sq.z * inv_n - mean * mean;
        o.z = ga.z * (h.z - mean) * rsqrtf(var + BN_EPS) + be.z;
    }
    {
        float mean = sm.w * inv_n; float var = sq.w * inv_n - mean * mean;
        o.w = ga.w * (h.w - mean) * rsqrtf(var + BN_EPS) + be.w;
    }
    *(float4*)&out[(size_t)idx * 4] = o;
}

// =================================================================================
extern "C" void kernel_launch(void* const* d_in, const int* in_sizes, int n_in,
                              void* d_out, int out_size)
{
    const float* x     = (const float*)d_in[0];
    const void*  ei    = d_in[1];
    const float* W_msg = (const float*)d_in[2];
    const float* b_msg = (const float*)d_in[3];
    const float* W_att = (const float*)d_in[4];
    const float* b_att = (const float*)d_in[5];
    const float* W_ih  = (const float*)d_in[6];
    const float* b_ih  = (const float*)d_in[7];
    const float* W_hh  = (const float*)d_in[8];
    const float* b_hh  = (const float*)d_in[9];
    const float* gamma = (const float*)d_in[10];
    const float* beta  = (const float*)d_in[11];
    float* out = (float*)d_out;

    const int E = in_sizes[1] / 2;

    detect_kernel<<<1, 1>>>(ei, E);
    node_pre_kernel<<<NP / 64, 256>>>(x, W_msg, b_msg, W_att);
    edge_kernel<<<(E * 32 + 255) / 256, 256>>>(ei, b_att, E);
    gemm_kernel<<<dim3(6, NP / 128), 256>>>(W_ih, W_hh, b_ih, b_hh);
    gru_kernel<<<NP / 128, 256>>>(x);
    bn_kernel<<<(N_NODES * 32 + 255) / 256, 256>>>(gamma, beta, out);
}

// round 3
// speedup vs baseline: 1.0494x; 1.0494x over previous
#include <cuda_runtime.h>
#include <cstdint>
#include <cstddef>

// Problem constants
#define N_NODES 50000
#define NP      50048          // padded to 782*64 = 391*128
#define D       128
#define BN_EPS  1e-5f

// ---------------- scratch (static device globals; no runtime alloc) -------------
__device__ float g_x  [(size_t)NP * D];      // padded copy of x
__device__ float g_m  [(size_t)NP * D];      // per-node message precompute x@W_msg+b
__device__ float g_as [NP];                  // x . W_att[:d]
__device__ float g_ad [NP];                  // x . W_att[d:]
__device__ float g_agg[(size_t)NP * D];      // scatter-add target
__device__ float g_g  [(size_t)NP * 768];    // [gi(384) | gh(384)] per node
__device__ float g_h  [(size_t)NP * D];      // h_new before BN
__device__ float g_sum[D];
__device__ float g_ssq[D];
__device__ int   g_is64;                     // edge_index dtype flag

__device__ __forceinline__ float sigm(float v) { return 1.f / (1.f + __expf(-v)); }

// =================================================================================
// Kernel 0: detect edge_index dtype (int32 vs int64).
// =================================================================================
__global__ void detect_kernel(const void* ei_raw, int E)
{
    const long long* e64 = (const long long*)ei_raw;
    int n = E < 64 ? E : 64;
    int ok = 1;
    for (int i = 0; i < n; i++) {
        long long v = e64[i];
        if (v < 0 || v >= N_NODES) { ok = 0; break; }
    }
    g_is64 = ok;
}

// =================================================================================
// Kernel A: per-node precompute (x copy, m = x@W_msg+b, attention pre-dots, zeroing)
// =================================================================================
__global__ __launch_bounds__(256) void node_pre_kernel(
    const float* __restrict__ x, const float* __restrict__ W_msg,
    const float* __restrict__ b_msg, const float* __restrict__ W_att)
{
    __shared__ __align__(16) float xs[64][132];   // node-major x tile (padded stride)
    __shared__ __align__(16) float Wc[16][128];   // W_msg k-chunk
    __shared__ float Was[128], Wad[128];

    const int tid = threadIdx.x;
    const int n0  = blockIdx.x * 64;

    if (tid < 128) { Was[tid] = W_att[tid]; Wad[tid] = W_att[128 + tid]; }

    for (int i = tid; i < 64 * 32; i += 256) {
        int node = i >> 5, cq = i & 31;
        float4 v = make_float4(0.f, 0.f, 0.f, 0.f);
        int gn = n0 + node;
        if (gn < N_NODES) v = *(const float4*)&x[(size_t)gn * D + cq * 4];
        *(float4*)&xs[node][cq * 4] = v;
        *(float4*)&g_x[(size_t)gn * D + cq * 4] = v;
    }
    for (int i = tid; i < 64 * 32; i += 256)
        *(float4*)&g_agg[(size_t)n0 * D + i * 4] = make_float4(0.f, 0.f, 0.f, 0.f);
    if (blockIdx.x == 0 && tid < 128) { g_sum[tid] = 0.f; g_ssq[tid] = 0.f; }

    const int tr = tid >> 4;
    const int tc = tid & 15;
    const int nt = tr * 4, c0 = tc * 8;
    float acc[4][8];
#pragma unroll
    for (int i = 0; i < 4; i++)
#pragma unroll
        for (int j = 0; j < 8; j++) acc[i][j] = 0.f;

    for (int kc = 0; kc < 8; kc++) {
        __syncthreads();
        for (int i = tid; i < 512; i += 256) {
            int kk = i >> 5, cq = i & 31;
            *(float4*)&Wc[kk][cq * 4] =
                *(const float4*)&W_msg[(size_t)(kc * 16 + kk) * D + cq * 4];
        }
        __syncthreads();
#pragma unroll
        for (int kk = 0; kk < 16; kk++) {
            int k = kc * 16 + kk;
            float xv0 = xs[nt + 0][k], xv1 = xs[nt + 1][k];
            float xv2 = xs[nt + 2][k], xv3 = xs[nt + 3][k];
            float4 w0 = *(const float4*)&Wc[kk][c0];
            float4 w1 = *(const float4*)&Wc[kk][c0 + 4];
            float wv[8] = {w0.x, w0.y, w0.z, w0.w, w1.x, w1.y, w1.z, w1.w};
#pragma unroll
            for (int j = 0; j < 8; j++) {
                acc[0][j] += xv0 * wv[j]; acc[1][j] += xv1 * wv[j];
                acc[2][j] += xv2 * wv[j]; acc[3][j] += xv3 * wv[j];
            }
        }
    }

    float bm[8];
#pragma unroll
    for (int j = 0; j < 8; j++) bm[j] = b_msg[c0 + j];
#pragma unroll
    for (int i = 0; i < 4; i++) {
        int n = n0 + nt + i;
        float4 v0 = make_float4(acc[i][0] + bm[0], acc[i][1] + bm[1],
                                acc[i][2] + bm[2], acc[i][3] + bm[3]);
        float4 v1 = make_float4(acc[i][4] + bm[4], acc[i][5] + bm[5],
                                acc[i][6] + bm[6], acc[i][7] + bm[7]);
        *(float4*)&g_m[(size_t)n * D + c0]     = v0;
        *(float4*)&g_m[(size_t)n * D + c0 + 4] = v1;
    }

    if (tid < 128) {
        int node = tid >> 1, sel = tid & 1;
        const float* wv = sel ? Wad : Was;
        float a0 = 0.f, a1 = 0.f, a2 = 0.f, a3 = 0.f;
#pragma unroll 8
        for (int k = 0; k < 128; k += 4) {
            a0 += xs[node][k]     * wv[k];
            a1 += xs[node][k + 1] * wv[k + 1];
            a2 += xs[node][k + 2] * wv[k + 2];
            a3 += xs[node][k + 3] * wv[k + 3];
        }
        float r = (a0 + a1) + (a2 + a3);
        if (sel) g_ad[n0 + node] = r; else g_as[n0 + node] = r;
    }
}

// =================================================================================
// Kernel B: edge pass. One warp per edge, red.global.add.v4.f32 scatter.
// =================================================================================
__global__ __launch_bounds__(256) void edge_kernel(
    const void* __restrict__ ei_raw, const float* __restrict__ b_att, int E)
{
    int gw   = (blockIdx.x * blockDim.x + threadIdx.x) >> 5;
    int lane = threadIdx.x & 31;
    if (gw >= E) return;

    int src, dst;
    if (g_is64) {
        const long long* e = (const long long*)ei_raw;
        src = (int)e[gw];
        dst = (int)e[(size_t)E + gw];
    } else {
        const int* e = (const int*)ei_raw;
        src = e[gw];
        dst = e[E + gw];
    }
    if ((unsigned)src >= N_NODES || (unsigned)dst >= N_NODES) return;

    float att = sigm(g_as[src] + g_ad[dst] + b_att[0]);

    float4 v = *(const float4*)&g_m[(size_t)src * D + lane * 4];
    float* o = &g_agg[(size_t)dst * D + lane * 4];
    asm volatile("red.global.add.v4.f32 [%0], {%1, %2, %3, %4};"
                 :: "l"(o), "f"(v.x * att), "f"(v.y * att),
                    "f"(v.z * att), "f"(v.w * att)
                 : "memory");
}

// =================================================================================
// Kernel C: GEMM  g_g[NP, 768].  cols [0,384)=agg@W_ih^T, [384,768)=x@W_hh^T.
// 128x128 tile per block, 256 thr, 8x8 frags, k-chunks of 16.
// Double-buffered smem (one __syncthreads per chunk), 2 blocks/SM.
// =================================================================================
__global__ __launch_bounds__(256, 2) void gemm_kernel(
    const float* __restrict__ W_ih, const float* __restrict__ W_hh,
    const float* __restrict__ b_ih, const float* __restrict__ b_hh)
{
    __shared__ __align__(16) float As[2][16][132];
    __shared__ __align__(16) float Bs[2][16][132];

    const int bx = blockIdx.x, tid = threadIdx.x;
    const int n0 = blockIdx.y * 128;
    const bool ih = (bx < 3);
    const float* A = ih ? g_agg : g_x;
    const float* W = ih ? W_ih : W_hh;
    const float* bptr = ih ? b_ih : b_hh;
    const int wro = (ih ? bx : bx - 3) * 128;

    const int tr = tid >> 4, tc = tid & 15;
    // load coords: i in {tid, tid+256}; node/row = i>>2, kq = i&3
    const int ln0 = tid >> 2, lkq = tid & 3;

    float acc[8][8];
#pragma unroll
    for (int i = 0; i < 8; i++)
#pragma unroll
        for (int j = 0; j < 8; j++) acc[i][j] = 0.f;

    // ---- preload chunk 0 into stage 0 ----
    {
        const int k0 = 0;
        float4 va0 = *(const float4*)&A[(size_t)(n0 + ln0) * D + k0 + lkq * 4];
        float4 va1 = *(const float4*)&A[(size_t)(n0 + 64 + ln0) * D + k0 + lkq * 4];
        float4 vb0 = *(const float4*)&W[(size_t)(wro + ln0) * D + k0 + lkq * 4];
        float4 vb1 = *(const float4*)&W[(size_t)(wro + 64 + ln0) * D + k0 + lkq * 4];
        As[0][lkq * 4 + 0][ln0] = va0.x; As[0][lkq * 4 + 1][ln0] = va0.y;
        As[0][lkq * 4 + 2][ln0] = va0.z; As[0][lkq * 4 + 3][ln0] = va0.w;
        As[0][lkq * 4 + 0][64 + ln0] = va1.x; As[0][lkq * 4 + 1][64 + ln0] = va1.y;
        As[0][lkq * 4 + 2][64 + ln0] = va1.z; As[0][lkq * 4 + 3][64 + ln0] = va1.w;
        Bs[0][lkq * 4 + 0][ln0] = vb0.x; Bs[0][lkq * 4 + 1][ln0] = vb0.y;
        Bs[0][lkq * 4 + 2][ln0] = vb0.z; Bs[0][lkq * 4 + 3][ln0] = vb0.w;
        Bs[0][lkq * 4 + 0][64 + ln0] = vb1.x; Bs[0][lkq * 4 + 1][64 + ln0] = vb1.y;
        Bs[0][lkq * 4 + 2][64 + ln0] = vb1.z; Bs[0][lkq * 4 + 3][64 + ln0] = vb1.w;
    }
    __syncthreads();

#pragma unroll 1
    for (int kc = 0; kc < 8; kc++) {
        const int s = kc & 1;
        // issue loads for next chunk into the other stage (safe: that stage's
        // readers finished before the sync that ended iteration kc-1)
        if (kc < 7) {
            const int k0 = (kc + 1) * 16;
            float4 va0 = *(const float4*)&A[(size_t)(n0 + ln0) * D + k0 + lkq * 4];
            float4 va1 = *(const float4*)&A[(size_t)(n0 + 64 + ln0) * D + k0 + lkq * 4];
            float4 vb0 = *(const float4*)&W[(size_t)(wro + ln0) * D + k0 + lkq * 4];
            float4 vb1 = *(const float4*)&W[(size_t)(wro + 64 + ln0) * D + k0 + lkq * 4];
            const int d = s ^ 1;
            As[d][lkq * 4 + 0][ln0] = va0.x; As[d][lkq * 4 + 1][ln0] = va0.y;
            As[d][lkq * 4 + 2][ln0] = va0.z; As[d][lkq * 4 + 3][ln0] = va0.w;
            As[d][lkq * 4 + 0][64 + ln0] = va1.x; As[d][lkq * 4 + 1][64 + ln0] = va1.y;
            As[d][lkq * 4 + 2][64 + ln0] = va1.z; As[d][lkq * 4 + 3][64 + ln0] = va1.w;
            Bs[d][lkq * 4 + 0][ln0] = vb0.x; Bs[d][lkq * 4 + 1][ln0] = vb0.y;
            Bs[d][lkq * 4 + 2][ln0] = vb0.z; Bs[d][lkq * 4 + 3][ln0] = vb0.w;
            Bs[d][lkq * 4 + 0][64 + ln0] = vb1.x; Bs[d][lkq * 4 + 1][64 + ln0] = vb1.y;
            Bs[d][lkq * 4 + 2][64 + ln0] = vb1.z; Bs[d][lkq * 4 + 3][64 + ln0] = vb1.w;
        }

        const float (*Asr)[132] = As[s];
        const float (*Bsr)[132] = Bs[s];
#pragma unroll
        for (int kk = 0; kk < 16; kk++) {
            float4 a0 = *(const float4*)&Asr[kk][tr * 8];
            float4 a1 = *(const float4*)&Asr[kk][tr * 8 + 4];
            float4 b0 = *(const float4*)&Bsr[kk][tc * 8];
            float4 b1 = *(const float4*)&Bsr[kk][tc * 8 + 4];
            float a[8] = {a0.x, a0.y, a0.z, a0.w, a1.x, a1.y, a1.z, a1.w};
            float b[8] = {b0.x, b0.y, b0.z, b0.w, b1.x, b1.y, b1.z, b1.w};
#pragma unroll
            for (int i = 0; i < 8; i++)
#pragma unroll
                for (int j = 0; j < 8; j++) acc[i][j] += a[i] * b[j];
        }
        __syncthreads();
    }

    float bias[8];
#pragma unroll
    for (int j = 0; j < 8; j++) bias[j] = bptr[wro + tc * 8 + j];
#pragma unroll
    for (int i = 0; i < 8; i++) {
        int n = n0 + tr * 8 + i;
        size_t base = (size_t)n * 768 + bx * 128 + tc * 8;
        float4 v0 = make_float4(acc[i][0] + bias[0], acc[i][1] + bias[1],
                                acc[i][2] + bias[2], acc[i][3] + bias[3]);
        float4 v1 = make_float4(acc[i][4] + bias[4], acc[i][5] + bias[5],
                                acc[i][6] + bias[6], acc[i][7] + bias[7]);
        *(float4*)&g_g[base]     = v0;
        *(float4*)&g_g[base + 4] = v1;
    }
}

// =================================================================================
// Kernel D: GRU elementwise + BN column-stat accumulation.
// =================================================================================
__global__ __launch_bounds__(256) void gru_kernel(const float* __restrict__ x)
{
    __shared__ float rs_[8][128];
    __shared__ float rq_[8][128];

    const int tid = threadIdx.x;
    const int c4 = tid & 31;
    const int rs = tid >> 5;
    float4 s = make_float4(0.f, 0.f, 0.f, 0.f);
    float4 q = make_float4(0.f, 0.f, 0.f, 0.f);

    for (int it = 0; it < 16; it++) {
        int n = blockIdx.x * 128 + it * 8 + rs;
        if (n >= N_NODES) break;
        size_t gb = (size_t)n * 768 + c4 * 4;
        float4 ir = *(const float4*)&g_g[gb];
        float4 iz = *(const float4*)&g_g[gb + 128];
        float4 in_ = *(const float4*)&g_g[gb + 256];
        float4 hr = *(const float4*)&g_g[gb + 384];
        float4 hz = *(const float4*)&g_g[gb + 512];
        float4 hn = *(const float4*)&g_g[gb + 640];
        float4 xv = *(const float4*)&x[(size_t)n * D + c4 * 4];

        float4 h;
        {
            float r = sigm(ir.x + hr.x), z = sigm(iz.x + hz.x);
            float nn = tanhf(in_.x + r * hn.x); h.x = (1.f - z) * nn + z * xv.x;
        }
        {
            float r = sigm(ir.y + hr.y), z = sigm(iz.y + hz.y);
            float nn = tanhf(in_.y + r * hn.y); h.y = (1.f - z) * nn + z * xv.y;
        }
        {
            float r = sigm(ir.z + hr.z), z = sigm(iz.z + hz.z);
            float nn = tanhf(in_.z + r * hn.z); h.z = (1.f - z) * nn + z * xv.z;
        }
        {
            float r = sigm(ir.w + hr.w), z = sigm(iz.w + hz.w);
            float nn = tanhf(in_.w + r * hn.w); h.w = (1.f - z) * nn + z * xv.w;
        }
        *(float4*)&g_h[(size_t)n * D + c4 * 4] = h;
        s.x += h.x; s.y += h.y; s.z += h.z; s.w += h.w;
        q.x += h.x * h.x; q.y += h.y * h.y; q.z += h.z * h.z; q.w += h.w * h.w;
    }

    *(float4*)&rs_[rs][c4 * 4] = s;
    *(float4*)&rq_[rs][c4 * 4] = q;
    __syncthreads();
    if (tid < 128) {
        float a = 0.f, b = 0.f;
#pragma unroll
        for (int r = 0; r < 8; r++) { a += rs_[r][tid]; b += rq_[r][tid]; }
        atomicAdd(&g_sum[tid], a);
        atomicAdd(&g_ssq[tid], b);
    }
}

// =================================================================================
// Kernel E: BatchNorm normalize.
// =================================================================================
__global__ __launch_bounds__(256) void bn_kernel(
    const float* __restrict__ gamma, const float* __restrict__ beta,
    float* __restrict__ out)
{
    int idx = blockIdx.x * 256 + threadIdx.x;
    if (idx >= N_NODES * 32) return;
    int c4 = idx & 31;
    const float inv_n = 1.f / (float)N_NODES;

    float4 h  = *(const float4*)&g_h[(size_t)idx * 4];
    float4 sm = *(const float4*)&g_sum[c4 * 4];
    float4 sq = *(const float4*)&g_ssq[c4 * 4];
    float4 ga = *(const float4*)&gamma[c4 * 4];
    float4 be = *(const float4*)&beta[c4 * 4];

    float4 o;
    {
        float mean = sm.x * inv_n; float var = sq.x * inv_n - mean * mean;
        o.x = ga.x * (h.x - mean) * rsqrtf(var + BN_EPS) + be.x;
    }
    {
        float mean = sm.y * inv_n; float var = sq.y * inv_n - mean * mean;
        o.y = ga.y * (h.y - mean) * rsqrtf(var + BN_EPS) + be.y;
    }
    {
        float mean = sm.z * inv_n; float var = sq.z * inv_n - mean * mean;
        o.z = ga.z * (h.z - mean) * rsqrtf(var + BN_EPS) + be.z;
    }
    {
        float mean = sm.w * inv_n; float var = sq.w * inv_n - mean * mean;
        o.w = ga.w * (h.w - mean) * rsqrtf(var + BN_EPS) + be.w;
    }
    *(float4*)&out[(size_t)idx * 4] = o;
}

// =================================================================================
extern "C" void kernel_launch(void* const* d_in, const int* in_sizes, int n_in,
                              void* d_out, int out_size)
{
    const float* x     = (const float*)d_in[0];
    const void*  ei    = d_in[1];
    const float* W_msg = (const float*)d_in[2];
    const float* b_msg = (const float*)d_in[3];
    const float* W_att = (const float*)d_in[4];
    const float* b_att = (const float*)d_in[5];
    const float* W_ih  = (const float*)d_in[6];
    const float* b_ih  = (const float*)d_in[7];
    const float* W_hh  = (const float*)d_in[8];
    const float* b_hh  = (const float*)d_in[9];
    const float* gamma = (const float*)d_in[10];
    const float* beta  = (const float*)d_in[11];
    float* out = (float*)d_out;

    const int E = in_sizes[1] / 2;

    detect_kernel<<<1, 1>>>(ei, E);
    node_pre_kernel<<<NP / 64, 256>>>(x, W_msg, b_msg, W_att);
    edge_kernel<<<(E * 32 + 255) / 256, 256>>>(ei, b_att, E);
    gemm_kernel<<<dim3(6, NP / 128), 256>>>(W_ih, W_hh, b_ih, b_hh);
    gru_kernel<<<NP / 128, 256>>>(x);
    bn_kernel<<<(N_NODES * 32 + 255) / 256, 256>>>(gamma, beta, out);
}

// round 5
// speedup vs baseline: 1.2864x; 1.2258x over previous
#include <cuda_runtime.h>
#include <cuda_bf16.h>
#include <cstdint>
#include <cstddef>

// Problem constants
#define N_NODES 50000
#define NP      50048          // padded: 782*64 = 391*128
#define D       128
#define BN_EPS  1e-5f

// ---------------- scratch (static device globals; no runtime alloc) -------------
__device__ float g_x  [(size_t)NP * D];
__device__ float g_m  [(size_t)NP * D];
__device__ float g_as [NP];
__device__ float g_ad [NP];
__device__ float g_agg[(size_t)NP * D];
__device__ float g_g  [(size_t)NP * 768];
__device__ float g_h  [(size_t)NP * D];
__device__ float g_sum[D];
__device__ float g_ssq[D];
__device__ int   g_is64;

// bf16 hi/lo planes for tensor-core GEMM
__device__ __nv_bfloat16 g_xh  [(size_t)NP * D];
__device__ __nv_bfloat16 g_xl  [(size_t)NP * D];
__device__ __nv_bfloat16 g_agh [(size_t)NP * D];
__device__ __nv_bfloat16 g_agl [(size_t)NP * D];
__device__ __nv_bfloat16 g_wh  [768 * D];    // [W_ih(384) ; W_hh(384)] hi
__device__ __nv_bfloat16 g_wl  [768 * D];    // lo

__device__ __forceinline__ float sigm(float v) { return 1.f / (1.f + __expf(-v)); }

// =================================================================================
// Kernel 0: detect edge_index dtype (int32 vs int64).
// =================================================================================
__global__ void detect_kernel(const void* ei_raw, int E)
{
    const long long* e64 = (const long long*)ei_raw;
    int n = E < 64 ? E : 64;
    int ok = 1;
    for (int i = 0; i < n; i++) {
        long long v = e64[i];
        if (v < 0 || v >= N_NODES) { ok = 0; break; }
    }
    g_is64 = ok;
}

// =================================================================================
// Kernel A: per-node precompute + x bf16 hi/lo planes.
// =================================================================================
__global__ __launch_bounds__(256) void node_pre_kernel(
    const float* __restrict__ x, const float* __restrict__ W_msg,
    const float* __restrict__ b_msg, const float* __restrict__ W_att)
{
    __shared__ __align__(16) float xs[64][132];
    __shared__ __align__(16) float Wc[16][128];
    __shared__ float Was[128], Wad[128];

    const int tid = threadIdx.x;
    const int n0  = blockIdx.x * 64;

    if (tid < 128) { Was[tid] = W_att[tid]; Wad[tid] = W_att[128 + tid]; }

    for (int i = tid; i < 64 * 32; i += 256) {
        int node = i >> 5, cq = i & 31;
        float4 v = make_float4(0.f, 0.f, 0.f, 0.f);
        int gn = n0 + node;
        if (gn < N_NODES) v = *(const float4*)&x[(size_t)gn * D + cq * 4];
        *(float4*)&xs[node][cq * 4] = v;
        *(float4*)&g_x[(size_t)gn * D + cq * 4] = v;
        __nv_bfloat162 h01, h23, l01, l23;
        h01.x = __float2bfloat16(v.x); l01.x = __float2bfloat16(v.x - __bfloat162float(h01.x));
        h01.y = __float2bfloat16(v.y); l01.y = __float2bfloat16(v.y - __bfloat162float(h01.y));
        h23.x = __float2bfloat16(v.z); l23.x = __float2bfloat16(v.z - __bfloat162float(h23.x));
        h23.y = __float2bfloat16(v.w); l23.y = __float2bfloat16(v.w - __bfloat162float(h23.y));
        *(__nv_bfloat162*)&g_xh[(size_t)gn * D + cq * 4]     = h01;
        *(__nv_bfloat162*)&g_xh[(size_t)gn * D + cq * 4 + 2] = h23;
        *(__nv_bfloat162*)&g_xl[(size_t)gn * D + cq * 4]     = l01;
        *(__nv_bfloat162*)&g_xl[(size_t)gn * D + cq * 4 + 2] = l23;
    }
    for (int i = tid; i < 64 * 32; i += 256)
        *(float4*)&g_agg[(size_t)n0 * D + i * 4] = make_float4(0.f, 0.f, 0.f, 0.f);
    if (blockIdx.x == 0 && tid < 128) { g_sum[tid] = 0.f; g_ssq[tid] = 0.f; }

    const int tr = tid >> 4;
    const int tc = tid & 15;
    const int nt = tr * 4, c0 = tc * 8;
    float acc[4][8];
#pragma unroll
    for (int i = 0; i < 4; i++)
#pragma unroll
        for (int j = 0; j < 8; j++) acc[i][j] = 0.f;

    for (int kc = 0; kc < 8; kc++) {
        __syncthreads();
        for (int i = tid; i < 512; i += 256) {
            int kk = i >> 5, cq = i & 31;
            *(float4*)&Wc[kk][cq * 4] =
                *(const float4*)&W_msg[(size_t)(kc * 16 + kk) * D + cq * 4];
        }
        __syncthreads();
#pragma unroll
        for (int kk = 0; kk < 16; kk++) {
            int k = kc * 16 + kk;
            float xv0 = xs[nt + 0][k], xv1 = xs[nt + 1][k];
            float xv2 = xs[nt + 2][k], xv3 = xs[nt + 3][k];
            float4 w0 = *(const float4*)&Wc[kk][c0];
            float4 w1 = *(const float4*)&Wc[kk][c0 + 4];
            float wv[8] = {w0.x, w0.y, w0.z, w0.w, w1.x, w1.y, w1.z, w1.w};
#pragma unroll
            for (int j = 0; j < 8; j++) {
                acc[0][j] += xv0 * wv[j]; acc[1][j] += xv1 * wv[j];
                acc[2][j] += xv2 * wv[j]; acc[3][j] += xv3 * wv[j];
            }
        }
    }

    float bm[8];
#pragma unroll
    for (int j = 0; j < 8; j++) bm[j] = b_msg[c0 + j];
#pragma unroll
    for (int i = 0; i < 4; i++) {
        int n = n0 + nt + i;
        float4 v0 = make_float4(acc[i][0] + bm[0], acc[i][1] + bm[1],
                                acc[i][2] + bm[2], acc[i][3] + bm[3]);
        float4 v1 = make_float4(acc[i][4] + bm[4], acc[i][5] + bm[5],
                                acc[i][6] + bm[6], acc[i][7] + bm[7]);
        *(float4*)&g_m[(size_t)n * D + c0]     = v0;
        *(float4*)&g_m[(size_t)n * D + c0 + 4] = v1;
    }

    if (tid < 128) {
        int node = tid >> 1, sel = tid & 1;
        const float* wv = sel ? Wad : Was;
        float a0 = 0.f, a1 = 0.f, a2 = 0.f, a3 = 0.f;
#pragma unroll 8
        for (int k = 0; k < 128; k += 4) {
            a0 += xs[node][k]     * wv[k];
            a1 += xs[node][k + 1] * wv[k + 1];
            a2 += xs[node][k + 2] * wv[k + 2];
            a3 += xs[node][k + 3] * wv[k + 3];
        }
        float r = (a0 + a1) + (a2 + a3);
        if (sel) g_ad[n0 + node] = r; else g_as[n0 + node] = r;
    }
}

// =================================================================================
// Kernel B: edge pass (warp/edge, red.global.add.v4.f32 scatter).
// =================================================================================
__global__ __launch_bounds__(256) void edge_kernel(
    const void* __restrict__ ei_raw, const float* __restrict__ b_att, int E)
{
    int gw   = (blockIdx.x * blockDim.x + threadIdx.x) >> 5;
    int lane = threadIdx.x & 31;
    if (gw >= E) return;

    int src, dst;
    if (g_is64) {
        const long long* e = (const long long*)ei_raw;
        src = (int)e[gw];
        dst = (int)e[(size_t)E + gw];
    } else {
        const int* e = (const int*)ei_raw;
        src = e[gw];
        dst = e[E + gw];
    }
    if ((unsigned)src >= N_NODES || (unsigned)dst >= N_NODES) return;

    float att = sigm(g_as[src] + g_ad[dst] + b_att[0]);

    float4 v = *(const float4*)&g_m[(size_t)src * D + lane * 4];
    float* o = &g_agg[(size_t)dst * D + lane * 4];
    asm volatile("red.global.add.v4.f32 [%0], {%1, %2, %3, %4};"
                 :: "l"(o), "f"(v.x * att), "f"(v.y * att),
                    "f"(v.z * att), "f"(v.w * att)
                 : "memory");
}

// =================================================================================
// Kernel B2: convert agg -> bf16 hi/lo planes; also W_ih/W_hh -> stacked planes.
// =================================================================================
#define CVT_AGG_Q (NP * 32)
#define CVT_W_Q   (768 * 32)
__global__ __launch_bounds__(256) void convert_kernel(
    const float* __restrict__ W_ih, const float* __restrict__ W_hh)
{
    int idx = blockIdx.x * 256 + threadIdx.x;
    if (idx >= CVT_AGG_Q + CVT_W_Q) return;

    float4 v;
    __nv_bfloat16* dh;
    __nv_bfloat16* dl;
    size_t off;
    if (idx < CVT_AGG_Q) {
        off = (size_t)idx * 4;
        v = *(const float4*)&g_agg[off];
        dh = g_agh; dl = g_agl;
    } else {
        int w = idx - CVT_AGG_Q;
        int row = w >> 5, cq = w & 31;
        off = (size_t)row * D + cq * 4;
        v = (row < 384) ? *(const float4*)&W_ih[(size_t)row * D + cq * 4]
                        : *(const float4*)&W_hh[(size_t)(row - 384) * D + cq * 4];
        dh = g_wh; dl = g_wl;
    }
    __nv_bfloat162 h01, h23, l01, l23;
    h01.x = __float2bfloat16(v.x); l01.x = __float2bfloat16(v.x - __bfloat162float(h01.x));
    h01.y = __float2bfloat16(v.y); l01.y = __float2bfloat16(v.y - __bfloat162float(h01.y));
    h23.x = __float2bfloat16(v.z); l23.x = __float2bfloat16(v.z - __bfloat162float(h23.x));
    h23.y = __float2bfloat16(v.w); l23.y = __float2bfloat16(v.w - __bfloat162float(h23.y));
    *(__nv_bfloat162*)&dh[off]     = h01;
    *(__nv_bfloat162*)&dh[off + 2] = h23;
    *(__nv_bfloat162*)&dl[off]     = l01;
    *(__nv_bfloat162*)&dl[off + 2] = l23;
}

// =================================================================================
// Kernel C: split-bf16 GEMM via mma.sync (HMMA, works on compute_103 base).
// g_g[node, 0..383] = agg @ W_ih^T + b_ih ; g_g[node, 384..767] = x @ W_hh^T + b_hh.
// Block: 128 nodes x 64 stacked-W rows. bx in 0..11 selects 64-row W group
// (bx<6 -> agg/W_ih operand pair, else x/W_hh). 8 warps in 4(M) x 2(N) grid,
// warp tile 32x32 = 2x4 m16n8k16 tiles. 3 passes: Ah*Bh + Al*Bh + Ah*Bl.
// SMEM: A[128][264] bf16 (hi cols 0..127, lo 128..255, pad 8), B[64][264].
// =================================================================================
#define AS_STR 264
#define SMEM_A_BYTES (128 * AS_STR * 2)
#define SMEM_B_BYTES (64 * AS_STR * 2)
#define SMEM_GEMM (SMEM_A_BYTES + SMEM_B_BYTES)

__device__ __forceinline__ void mma16816(float* c, const uint32_t* a, const uint32_t* b) {
    asm volatile(
        "mma.sync.aligned.m16n8k16.row.col.f32.bf16.bf16.f32 "
        "{%0,%1,%2,%3}, {%4,%5,%6,%7}, {%8,%9}, {%0,%1,%2,%3};"
        : "+f"(c[0]), "+f"(c[1]), "+f"(c[2]), "+f"(c[3])
        : "r"(a[0]), "r"(a[1]), "r"(a[2]), "r"(a[3]), "r"(b[0]), "r"(b[1]));
}

__global__ __launch_bounds__(256) void gemm_mma_kernel(
    const float* __restrict__ b_ih, const float* __restrict__ b_hh)
{
    extern __shared__ __align__(16) __nv_bfloat16 smem[];
    __nv_bfloat16* sA = smem;                    // [128][AS_STR]
    __nv_bfloat16* sB = smem + 128 * AS_STR;     // [64][AS_STR]

    const int tid = threadIdx.x;
    const int bx = blockIdx.x;
    const int n0 = blockIdx.y * 128;
    const bool ih = (bx < 6);
    const int wr0 = bx * 64;

    // ---- load A planes: hi -> cols [0,128), lo -> [128,256) ----
    {
        const __nv_bfloat16* Ah = ih ? g_agh : g_xh;
        const __nv_bfloat16* Al = ih ? g_agl : g_xl;
#pragma unroll
        for (int it = 0; it < 8; it++) {
            int i = tid + it * 256;              // 2048 chunks of 8 bf16
            int row = i >> 4, col = (i & 15) * 8;
            size_t gsrc = (size_t)(n0 + row) * D + col;
            *(uint4*)&sA[row * AS_STR + col]       = *(const uint4*)&Ah[gsrc];
            *(uint4*)&sA[row * AS_STR + 128 + col] = *(const uint4*)&Al[gsrc];
        }
    }
    // ---- load B planes ----
    {
#pragma unroll
        for (int it = 0; it < 4; it++) {
            int i = tid + it * 256;              // 1024 chunks
            int row = i >> 4, col = (i & 15) * 8;
            size_t gsrc = (size_t)(wr0 + row) * D + col;
            *(uint4*)&sB[row * AS_STR + col]       = *(const uint4*)&g_wh[gsrc];
            *(uint4*)&sB[row * AS_STR + 128 + col] = *(const uint4*)&g_wl[gsrc];
        }
    }
    __syncthreads();

    const int wid  = tid >> 5;
    const int lane = tid & 31;
    const int wm = (wid & 3) * 32;       // warp row base in tile
    const int wn = (wid >> 2) * 32;      // warp col base in tile
    const int qr = lane >> 2;            // 0..7
    const int qc = (lane & 3) * 2;       // 0,2,4,6

    float c[2][4][4];
#pragma unroll
    for (int mt = 0; mt < 2; mt++)
#pragma unroll
        for (int nt = 0; nt < 4; nt++)
#pragma unroll
            for (int j = 0; j < 4; j++) c[mt][nt][j] = 0.f;

#pragma unroll
    for (int pass = 0; pass < 3; pass++) {
        const int kA = (pass == 1) ? 128 : 0;
        const int kB = (pass == 2) ? 128 : 0;
#pragma unroll
        for (int s = 0; s < 8; s++) {
            const int ka = kA + s * 16 + qc;
            const int kb = kB + s * 16 + qc;
            uint32_t a[2][4];
#pragma unroll
            for (int mt = 0; mt < 2; mt++) {
                int r = wm + mt * 16 + qr;
                a[mt][0] = *(const uint32_t*)&sA[r * AS_STR + ka];
                a[mt][1] = *(const uint32_t*)&sA[(r + 8) * AS_STR + ka];
                a[mt][2] = *(const uint32_t*)&sA[r * AS_STR + ka + 8];
                a[mt][3] = *(const uint32_t*)&sA[(r + 8) * AS_STR + ka + 8];
            }
            uint32_t b[4][2];
#pragma unroll
            for (int nt = 0; nt < 4; nt++) {
                int n = wn + nt * 8 + qr;
                b[nt][0] = *(const uint32_t*)&sB[n * AS_STR + kb];
                b[nt][1] = *(const uint32_t*)&sB[n * AS_STR + kb + 8];
            }
#pragma unroll
            for (int mt = 0; mt < 2; mt++)
#pragma unroll
                for (int nt = 0; nt < 4; nt++)
                    mma16816(c[mt][nt], a[mt], b[nt]);
        }
    }

    // ---- epilogue: bias + store to g_g ----
    const float* bias = ih ? b_ih : b_hh;
    const int bofs = ih ? wr0 : (wr0 - 384);
#pragma unroll
    for (int mt = 0; mt < 2; mt++) {
#pragma unroll
        for (int nt = 0; nt < 4; nt++) {
            int col = wn + nt * 8 + qc;          // 0..63 within group
            float b0 = bias[bofs + col], b1 = bias[bofs + col + 1];
            int r0 = n0 + wm + mt * 16 + qr;
            size_t g0 = (size_t)r0 * 768 + wr0 + col;
            size_t g1 = (size_t)(r0 + 8) * 768 + wr0 + col;
            *(float2*)&g_g[g0] = make_float2(c[mt][nt][0] + b0, c[mt][nt][1] + b1);
            *(float2*)&g_g[g1] = make_float2(c[mt][nt][2] + b0, c[mt][nt][3] + b1);
        }
    }
}

// =================================================================================
// Kernel D: GRU elementwise + BN column-stat accumulation.
// =================================================================================
__global__ __launch_bounds__(256) void gru_kernel(const float* __restrict__ x)
{
    __shared__ float rs_[8][128];
    __shared__ float rq_[8][128];

    const int tid = threadIdx.x;
    const int c4 = tid & 31;
    const int rs = tid >> 5;
    float4 s = make_float4(0.f, 0.f, 0.f, 0.f);
    float4 q = make_float4(0.f, 0.f, 0.f, 0.f);

    for (int it = 0; it < 16; it++) {
        int n = blockIdx.x * 128 + it * 8 + rs;
        if (n >= N_NODES) break;
        size_t gb = (size_t)n * 768 + c4 * 4;
        float4 ir = *(const float4*)&g_g[gb];
        float4 iz = *(const float4*)&g_g[gb + 128];
        float4 in_ = *(const float4*)&g_g[gb + 256];
        float4 hr = *(const float4*)&g_g[gb + 384];
        float4 hz = *(const float4*)&g_g[gb + 512];
        float4 hn = *(const float4*)&g_g[gb + 640];
        float4 xv = *(const float4*)&x[(size_t)n * D + c4 * 4];

        float4 h;
        {
            float r = sigm(ir.x + hr.x), z = sigm(iz.x + hz.x);
            float nn = tanhf(in_.x + r * hn.x); h.x = (1.f - z) * nn + z * xv.x;
        }
        {
            float r = sigm(ir.y + hr.y), z = sigm(iz.y + hz.y);
            float nn = tanhf(in_.y + r * hn.y); h.y = (1.f - z) * nn + z * xv.y;
        }
        {
            float r = sigm(ir.z + hr.z), z = sigm(iz.z + hz.z);
            float nn = tanhf(in_.z + r * hn.z); h.z = (1.f - z) * nn + z * xv.z;
        }
        {
            float r = sigm(ir.w + hr.w), z = sigm(iz.w + hz.w);
            float nn = tanhf(in_.w + r * hn.w); h.w = (1.f - z) * nn + z * xv.w;
        }
        *(float4*)&g_h[(size_t)n * D + c4 * 4] = h;
        s.x += h.x; s.y += h.y; s.z += h.z; s.w += h.w;
        q.x += h.x * h.x; q.y += h.y * h.y; q.z += h.z * h.z; q.w += h.w * h.w;
    }

    *(float4*)&rs_[rs][c4 * 4] = s;
    *(float4*)&rq_[rs][c4 * 4] = q;
    __syncthreads();
    if (tid < 128) {
        float a = 0.f, b = 0.f;
#pragma unroll
        for (int r = 0; r < 8; r++) { a += rs_[r][tid]; b += rq_[r][tid]; }
        atomicAdd(&g_sum[tid], a);
        atomicAdd(&g_ssq[tid], b);
    }
}

// =================================================================================
// Kernel E: BatchNorm normalize.
// =================================================================================
__global__ __launch_bounds__(256) void bn_kernel(
    const float* __restrict__ gamma, const float* __restrict__ beta,
    float* __restrict__ out)
{
    int idx = blockIdx.x * 256 + threadIdx.x;
    if (idx >= N_NODES * 32) return;
    int c4 = idx & 31;
    const float inv_n = 1.f / (float)N_NODES;

    float4 h  = *(const float4*)&g_h[(size_t)idx * 4];
    float4 sm = *(const float4*)&g_sum[c4 * 4];
    float4 sq = *(const float4*)&g_ssq[c4 * 4];
    float4 ga = *(const float4*)&gamma[c4 * 4];
    float4 be = *(const float4*)&beta[c4 * 4];

    float4 o;
    {
        float mean = sm.x * inv_n; float var = sq.x * inv_n - mean * mean;
        o.x = ga.x * (h.x - mean) * rsqrtf(var + BN_EPS) + be.x;
    }
    {
        float mean = sm.y * inv_n; float var = sq.y * inv_n - mean * mean;
        o.y = ga.y * (h.y - mean) * rsqrtf(var + BN_EPS) + be.y;
    }
    {
        float mean = sm.z * inv_n; float var = sq.z * inv_n - mean * mean;
        o.z = ga.z * (h.z - mean) * rsqrtf(var + BN_EPS) + be.z;
    }
    {
        float mean = sm.w * inv_n; float var = sq.w * inv_n - mean * mean;
        o.w = ga.w * (h.w - mean) * rsqrtf(var + BN_EPS) + be.w;
    }
    *(float4*)&out[(size_t)idx * 4] = o;
}

// =================================================================================
extern "C" void kernel_launch(void* const* d_in, const int* in_sizes, int n_in,
                              void* d_out, int out_size)
{
    const float* x     = (const float*)d_in[0];
    const void*  ei    = d_in[1];
    const float* W_msg = (const float*)d_in[2];
    const float* b_msg = (const float*)d_in[3];
    const float* W_att = (const float*)d_in[4];
    const float* b_att = (const float*)d_in[5];
    const float* W_ih  = (const float*)d_in[6];
    const float* b_ih  = (const float*)d_in[7];
    const float* W_hh  = (const float*)d_in[8];
    const float* b_hh  = (const float*)d_in[9];
    const float* gamma = (const float*)d_in[10];
    const float* beta  = (const float*)d_in[11];
    float* out = (float*)d_out;

    const int E = in_sizes[1] / 2;

    static int smem_set = 0;
    if (!smem_set) {
        cudaFuncSetAttribute(gemm_mma_kernel,
                             cudaFuncAttributeMaxDynamicSharedMemorySize, SMEM_GEMM);
        smem_set = 1;
    }

    detect_kernel<<<1, 1>>>(ei, E);
    node_pre_kernel<<<NP / 64, 256>>>(x, W_msg, b_msg, W_att);
    edge_kernel<<<(E * 32 + 255) / 256, 256>>>(ei, b_att, E);
    convert_kernel<<<(CVT_AGG_Q + CVT_W_Q + 255) / 256, 256>>>(W_ih, W_hh);
    gemm_mma_kernel<<<dim3(12, NP / 128), 256, SMEM_GEMM>>>(b_ih, b_hh);
    gru_kernel<<<NP / 128, 256>>>(x);
    bn_kernel<<<(N_NODES * 32 + 255) / 256, 256>>>(gamma, beta, out);
}

// round 6
// speedup vs baseline: 1.5208x; 1.1822x over previous
#include <cuda_runtime.h>
#include <cuda_bf16.h>
#include <cstdint>
#include <cstddef>

// Problem constants
#define N_NODES 50000
#define NP      50048          // padded: 782*64 = 391*128
#define NSCAN   50176          // 196*256 for scan
#define D       128
#define E_MAX   800000
#define BN_EPS  1e-5f

// ---------------- scratch (static device globals; no runtime alloc) -------------
__device__ float g_x  [(size_t)NP * D];
__device__ float g_m  [(size_t)NP * D];
__device__ float g_as [NP];
__device__ float g_ad [NP];
__device__ float g_agg[(size_t)NP * D];
__device__ float g_g  [(size_t)NP * 768];
__device__ float g_h  [(size_t)NP * D];
__device__ float g_sum[D];
__device__ float g_ssq[D];
__device__ int   g_is64;

// CSR build for edge gather
__device__ int g_cnt [NSCAN];
__device__ int g_off [NSCAN];
__device__ int g_bsum[256];
__device__ int g_boff[256];
__device__ int g_start[NSCAN];
__device__ int g_cur [NSCAN];
__device__ int g_esrc[E_MAX];

// bf16 hi/lo planes for tensor-core GEMM
__device__ __nv_bfloat16 g_xh  [(size_t)NP * D];
__device__ __nv_bfloat16 g_xl  [(size_t)NP * D];
__device__ __nv_bfloat16 g_agh [(size_t)NP * D];
__device__ __nv_bfloat16 g_agl [(size_t)NP * D];
__device__ __nv_bfloat16 g_wh  [768 * D];
__device__ __nv_bfloat16 g_wl  [768 * D];

__device__ __forceinline__ float sigm(float v) { return 1.f / (1.f + __expf(-v)); }

__device__ __forceinline__ uint32_t smem_u32(const void* p) {
    uint32_t a;
    asm("{ .reg .u64 t; cvta.to.shared.u64 t, %1; cvt.u32.u64 %0, t; }" : "=r"(a) : "l"(p));
    return a;
}

// =================================================================================
// Kernel 0: detect edge_index dtype (int32 vs int64).
// =================================================================================
__global__ void detect_kernel(const void* ei_raw, int E)
{
    const long long* e64 = (const long long*)ei_raw;
    int n = E < 64 ? E : 64;
    int ok = 1;
    for (int i = 0; i < n; i++) {
        long long v = e64[i];
        if (v < 0 || v >= N_NODES) { ok = 0; break; }
    }
    g_is64 = ok;
}

__device__ __forceinline__ void load_edge(const void* ei_raw, int E, int e,
                                          int& src, int& dst)
{
    if (g_is64) {
        const long long* p = (const long long*)ei_raw;
        src = (int)p[e];
        dst = (int)p[(size_t)E + e];
    } else {
        const int* p = (const int*)ei_raw;
        src = p[e];
        dst = p[E + e];
    }
}

// =================================================================================
// Kernel A: per-node precompute + x bf16 hi/lo planes + counter zeroing.
// =================================================================================
__global__ __launch_bounds__(256) void node_pre_kernel(
    const float* __restrict__ x, const float* __restrict__ W_msg,
    const float* __restrict__ b_msg, const float* __restrict__ W_att)
{
    __shared__ __align__(16) float xs[64][132];
    __shared__ __align__(16) float Wc[16][128];
    __shared__ float Was[128], Wad[128];

    const int tid = threadIdx.x;
    const int n0  = blockIdx.x * 64;

    if (tid < 128) { Was[tid] = W_att[tid]; Wad[tid] = W_att[128 + tid]; }
    if (tid < 64) g_cnt[n0 + tid] = 0;
    if (blockIdx.x == 0) {
        if (tid < 128) { g_sum[tid] = 0.f; g_ssq[tid] = 0.f; g_cnt[NP + tid] = 0; }
    }

    for (int i = tid; i < 64 * 32; i += 256) {
        int node = i >> 5, cq = i & 31;
        float4 v = make_float4(0.f, 0.f, 0.f, 0.f);
        int gn = n0 + node;
        if (gn < N_NODES) v = *(const float4*)&x[(size_t)gn * D + cq * 4];
        *(float4*)&xs[node][cq * 4] = v;
        *(float4*)&g_x[(size_t)gn * D + cq * 4] = v;
        __nv_bfloat162 h01, h23, l01, l23;
        h01.x = __float2bfloat16(v.x); l01.x = __float2bfloat16(v.x - __bfloat162float(h01.x));
        h01.y = __float2bfloat16(v.y); l01.y = __float2bfloat16(v.y - __bfloat162float(h01.y));
        h23.x = __float2bfloat16(v.z); l23.x = __float2bfloat16(v.z - __bfloat162float(h23.x));
        h23.y = __float2bfloat16(v.w); l23.y = __float2bfloat16(v.w - __bfloat162float(h23.y));
        *(__nv_bfloat162*)&g_xh[(size_t)gn * D + cq * 4]     = h01;
        *(__nv_bfloat162*)&g_xh[(size_t)gn * D + cq * 4 + 2] = h23;
        *(__nv_bfloat162*)&g_xl[(size_t)gn * D + cq * 4]     = l01;
        *(__nv_bfloat162*)&g_xl[(size_t)gn * D + cq * 4 + 2] = l23;
    }

    const int tr = tid >> 4;
    const int tc = tid & 15;
    const int nt = tr * 4, c0 = tc * 8;
    float acc[4][8];
#pragma unroll
    for (int i = 0; i < 4; i++)
#pragma unroll
        for (int j = 0; j < 8; j++) acc[i][j] = 0.f;

    for (int kc = 0; kc < 8; kc++) {
        __syncthreads();
        for (int i = tid; i < 512; i += 256) {
            int kk = i >> 5, cq = i & 31;
            *(float4*)&Wc[kk][cq * 4] =
                *(const float4*)&W_msg[(size_t)(kc * 16 + kk) * D + cq * 4];
        }
        __syncthreads();
#pragma unroll
        for (int kk = 0; kk < 16; kk++) {
            int k = kc * 16 + kk;
            float xv0 = xs[nt + 0][k], xv1 = xs[nt + 1][k];
            float xv2 = xs[nt + 2][k], xv3 = xs[nt + 3][k];
            float4 w0 = *(const float4*)&Wc[kk][c0];
            float4 w1 = *(const float4*)&Wc[kk][c0 + 4];
            float wv[8] = {w0.x, w0.y, w0.z, w0.w, w1.x, w1.y, w1.z, w1.w};
#pragma unroll
            for (int j = 0; j < 8; j++) {
                acc[0][j] += xv0 * wv[j]; acc[1][j] += xv1 * wv[j];
                acc[2][j] += xv2 * wv[j]; acc[3][j] += xv3 * wv[j];
            }
        }
    }

    float bm[8];
#pragma unroll
    for (int j = 0; j < 8; j++) bm[j] = b_msg[c0 + j];
#pragma unroll
    for (int i = 0; i < 4; i++) {
        int n = n0 + nt + i;
        float4 v0 = make_float4(acc[i][0] + bm[0], acc[i][1] + bm[1],
                                acc[i][2] + bm[2], acc[i][3] + bm[3]);
        float4 v1 = make_float4(acc[i][4] + bm[4], acc[i][5] + bm[5],
                                acc[i][6] + bm[6], acc[i][7] + bm[7]);
        *(float4*)&g_m[(size_t)n * D + c0]     = v0;
        *(float4*)&g_m[(size_t)n * D + c0 + 4] = v1;
    }

    if (tid < 128) {
        int node = tid >> 1, sel = tid & 1;
        const float* wv = sel ? Wad : Was;
        float a0 = 0.f, a1 = 0.f, a2 = 0.f, a3 = 0.f;
#pragma unroll 8
        for (int k = 0; k < 128; k += 4) {
            a0 += xs[node][k]     * wv[k];
            a1 += xs[node][k + 1] * wv[k + 1];
            a2 += xs[node][k + 2] * wv[k + 2];
            a3 += xs[node][k + 3] * wv[k + 3];
        }
        float r = (a0 + a1) + (a2 + a3);
        if (sel) g_ad[n0 + node] = r; else g_as[n0 + node] = r;
    }
}

// =================================================================================
// CSR build: histogram -> scan (3 kernels) -> scatter.
// =================================================================================
__global__ __launch_bounds__(256) void hist_kernel(const void* __restrict__ ei, int E)
{
    int e = blockIdx.x * 256 + threadIdx.x;
    if (e >= E) return;
    int src, dst;
    load_edge(ei, E, e, src, dst);
    if ((unsigned)dst >= N_NODES) return;
    atomicAdd(&g_cnt[dst], 1);
}

__global__ __launch_bounds__(256) void scan_a_kernel()
{
    __shared__ int sh[256];
    const int tid = threadIdx.x;
    int t = blockIdx.x * 256 + tid;
    int v = g_cnt[t];
    sh[tid] = v; __syncthreads();
#pragma unroll
    for (int o = 1; o < 256; o <<= 1) {
        int u = (tid >= o) ? sh[tid - o] : 0;
        __syncthreads();
        sh[tid] += u;
        __syncthreads();
    }
    g_off[t] = sh[tid] - v;
    if (tid == 255) g_bsum[blockIdx.x] = sh[255];
}

__global__ __launch_bounds__(256) void scan_b_kernel()
{
    __shared__ int sh[256];
    const int tid = threadIdx.x;
    int v = (tid < NSCAN / 256) ? g_bsum[tid] : 0;
    sh[tid] = v; __syncthreads();
#pragma unroll
    for (int o = 1; o < 256; o <<= 1) {
        int u = (tid >= o) ? sh[tid - o] : 0;
        __syncthreads();
        sh[tid] += u;
        __syncthreads();
    }
    g_boff[tid] = sh[tid] - v;
}

__global__ __launch_bounds__(256) void scan_c_kernel()
{
    int t = blockIdx.x * 256 + threadIdx.x;
    int s = g_off[t] + g_boff[blockIdx.x];
    g_start[t] = s;
    g_cur[t]   = s;
}

__global__ __launch_bounds__(256) void scatter_kernel(const void* __restrict__ ei, int E)
{
    int e = blockIdx.x * 256 + threadIdx.x;
    if (e >= E) return;
    int src, dst;
    load_edge(ei, E, e, src, dst);
    if ((unsigned)src >= N_NODES || (unsigned)dst >= N_NODES) return;
    int p = atomicAdd(&g_cur[dst], 1);
    if (p < E) g_esrc[p] = src;
}

// =================================================================================
// Gather: one warp per dst node; sum att-weighted messages over in-edges.
// =================================================================================
__global__ __launch_bounds__(256) void gather_kernel(const float* __restrict__ b_att)
{
    const int wid  = threadIdx.x >> 5;
    const int lane = threadIdx.x & 31;
    const int n = blockIdx.x * 8 + wid;
    if (n >= NP) return;

    const int s0 = g_start[n];
    const int s1 = (n + 1 < NSCAN) ? g_start[n + 1] : s0;
    const float adb = ((n < N_NODES) ? g_ad[n] : 0.f) + b_att[0];

    float4 acc = make_float4(0.f, 0.f, 0.f, 0.f);
    int i = s0;
    for (; i + 1 < s1; i += 2) {
        int src0 = g_esrc[i], src1 = g_esrc[i + 1];
        float at0 = sigm(g_as[src0] + adb);
        float at1 = sigm(g_as[src1] + adb);
        float4 v0 = *(const float4*)&g_m[(size_t)src0 * D + lane * 4];
        float4 v1 = *(const float4*)&g_m[(size_t)src1 * D + lane * 4];
        acc.x += v0.x * at0 + v1.x * at1;
        acc.y += v0.y * at0 + v1.y * at1;
        acc.z += v0.z * at0 + v1.z * at1;
        acc.w += v0.w * at0 + v1.w * at1;
    }
    if (i < s1) {
        int src0 = g_esrc[i];
        float at0 = sigm(g_as[src0] + adb);
        float4 v0 = *(const float4*)&g_m[(size_t)src0 * D + lane * 4];
        acc.x += v0.x * at0; acc.y += v0.y * at0;
        acc.z += v0.z * at0; acc.w += v0.w * at0;
    }
    *(float4*)&g_agg[(size_t)n * D + lane * 4] = acc;
}

// =================================================================================
// Convert agg -> bf16 hi/lo planes; W_ih/W_hh -> stacked planes.
// =================================================================================
#define CVT_AGG_Q (NP * 32)
#define CVT_W_Q   (768 * 32)
__global__ __launch_bounds__(256) void convert_kernel(
    const float* __restrict__ W_ih, const float* __restrict__ W_hh)
{
    int idx = blockIdx.x * 256 + threadIdx.x;
    if (idx >= CVT_AGG_Q + CVT_W_Q) return;

    float4 v;
    __nv_bfloat16* dh;
    __nv_bfloat16* dl;
    size_t off;
    if (idx < CVT_AGG_Q) {
        off = (size_t)idx * 4;
        v = *(const float4*)&g_agg[off];
        dh = g_agh; dl = g_agl;
    } else {
        int w = idx - CVT_AGG_Q;
        int row = w >> 5, cq = w & 31;
        off = (size_t)row * D + cq * 4;
        v = (row < 384) ? *(const float4*)&W_ih[(size_t)row * D + cq * 4]
                        : *(const float4*)&W_hh[(size_t)(row - 384) * D + cq * 4];
        dh = g_wh; dl = g_wl;
    }
    __nv_bfloat162 h01, h23, l01, l23;
    h01.x = __float2bfloat16(v.x); l01.x = __float2bfloat16(v.x - __bfloat162float(h01.x));
    h01.y = __float2bfloat16(v.y); l01.y = __float2bfloat16(v.y - __bfloat162float(h01.y));
    h23.x = __float2bfloat16(v.z); l23.x = __float2bfloat16(v.z - __bfloat162float(h23.x));
    h23.y = __float2bfloat16(v.w); l23.y = __float2bfloat16(v.w - __bfloat162float(h23.y));
    *(__nv_bfloat162*)&dh[off]     = h01;
    *(__nv_bfloat162*)&dh[off + 2] = h23;
    *(__nv_bfloat162*)&dl[off]     = l01;
    *(__nv_bfloat162*)&dl[off + 2] = l23;
}

// =================================================================================
// GEMM via mma.sync + ldmatrix. Same tiling as R5 (proven layout), but fragment
// loads via ldmatrix.x4 (4 instr/k-step instead of 16 LDS).
// =================================================================================
#define AS_STR 264
#define SMEM_A_BYTES (128 * AS_STR * 2)
#define SMEM_B_BYTES (64 * AS_STR * 2)
#define SMEM_GEMM (SMEM_A_BYTES + SMEM_B_BYTES)

__device__ __forceinline__ void mma16816(float* c, const uint32_t* a, const uint32_t* b) {
    asm volatile(
        "mma.sync.aligned.m16n8k16.row.col.f32.bf16.bf16.f32 "
        "{%0,%1,%2,%3}, {%4,%5,%6,%7}, {%8,%9}, {%0,%1,%2,%3};"
        : "+f"(c[0]), "+f"(c[1]), "+f"(c[2]), "+f"(c[3])
        : "r"(a[0]), "r"(a[1]), "r"(a[2]), "r"(a[3]), "r"(b[0]), "r"(b[1]));
}
__device__ __forceinline__ void ldmx4(uint32_t* d, uint32_t addr) {
    asm volatile("ldmatrix.sync.aligned.m8n8.x4.shared.b16 {%0,%1,%2,%3}, [%4];"
                 : "=r"(d[0]), "=r"(d[1]), "=r"(d[2]), "=r"(d[3]) : "r"(addr));
}

__global__ __launch_bounds__(256) void gemm_mma_kernel(
    const float* __restrict__ b_ih, const float* __restrict__ b_hh)
{
    extern __shared__ __align__(16) __nv_bfloat16 smem[];
    __nv_bfloat16* sA = smem;                    // [128][AS_STR]
    __nv_bfloat16* sB = smem + 128 * AS_STR;     // [64][AS_STR]

    const int tid = threadIdx.x;
    const int bx = blockIdx.x;
    const int n0 = blockIdx.y * 128;
    const bool ih = (bx < 6);
    const int wr0 = bx * 64;

    {
        const __nv_bfloat16* Ah = ih ? g_agh : g_xh;
        const __nv_bfloat16* Al = ih ? g_agl : g_xl;
#pragma unroll
        for (int it = 0; it < 8; it++) {
            int i = tid + it * 256;
            int row = i >> 4, col = (i & 15) * 8;
            size_t gsrc = (size_t)(n0 + row) * D + col;
            *(uint4*)&sA[row * AS_STR + col]       = *(const uint4*)&Ah[gsrc];
            *(uint4*)&sA[row * AS_STR + 128 + col] = *(const uint4*)&Al[gsrc];
        }
#pragma unroll
        for (int it = 0; it < 4; it++) {
            int i = tid + it * 256;
            int row = i >> 4, col = (i & 15) * 8;
            size_t gsrc = (size_t)(wr0 + row) * D + col;
            *(uint4*)&sB[row * AS_STR + col]       = *(const uint4*)&g_wh[gsrc];
            *(uint4*)&sB[row * AS_STR + 128 + col] = *(const uint4*)&g_wl[gsrc];
        }
    }
    __syncthreads();

    const int wid  = tid >> 5;
    const int lane = tid & 31;
    const int wm = (wid & 3) * 32;
    const int wn = (wid >> 2) * 32;
    const int g  = lane >> 3;         // ldmatrix lane-group 0..3
    const int r  = lane & 7;
    const int qr = lane >> 2;
    const int qc = (lane & 3) * 2;

    // ldmatrix lane base addresses (bytes into shared)
    uint32_t aBase[2], bBase[2];
#pragma unroll
    for (int mt = 0; mt < 2; mt++) {
        int row = wm + mt * 16 + ((g & 1) ? 8 : 0) + r;
        int col = (g >= 2) ? 8 : 0;
        aBase[mt] = smem_u32(&sA[row * AS_STR + col]);
    }
#pragma unroll
    for (int ntp = 0; ntp < 2; ntp++) {
        int row = wn + (ntp * 2 + (g >> 1)) * 8 + r;
        int col = (g & 1) ? 8 : 0;
        bBase[ntp] = smem_u32(&sB[row * AS_STR + col]);
    }

    float c[2][4][4];
#pragma unroll
    for (int mt = 0; mt < 2; mt++)
#pragma unroll
        for (int nt = 0; nt < 4; nt++)
#pragma unroll
            for (int j = 0; j < 4; j++) c[mt][nt][j] = 0.f;

#pragma unroll
    for (int pass = 0; pass < 3; pass++) {
        const int kA = (pass == 1) ? 128 : 0;
        const int kB = (pass == 2) ? 128 : 0;
#pragma unroll
        for (int s = 0; s < 8; s++) {
            const uint32_t offA = (uint32_t)((kA + s * 16) * 2);
            const uint32_t offB = (uint32_t)((kB + s * 16) * 2);
            uint32_t a[2][4], b[2][4];
            ldmx4(a[0], aBase[0] + offA);
            ldmx4(a[1], aBase[1] + offA);
            ldmx4(b[0], bBase[0] + offB);   // {b0_lo,b0_hi,b1_lo,b1_hi} for nt 0,1
            ldmx4(b[1], bBase[1] + offB);   // nt 2,3
#pragma unroll
            for (int mt = 0; mt < 2; mt++) {
                mma16816(c[mt][0], a[mt], &b[0][0]);
                mma16816(c[mt][1], a[mt], &b[0][2]);
                mma16816(c[mt][2], a[mt], &b[1][0]);
                mma16816(c[mt][3], a[mt], &b[1][2]);
            }
        }
    }

    const float* bias = ih ? b_ih : b_hh;
    const int bofs = ih ? wr0 : (wr0 - 384);
#pragma unroll
    for (int mt = 0; mt < 2; mt++) {
#pragma unroll
        for (int nt = 0; nt < 4; nt++) {
            int col = wn + nt * 8 + qc;
            float b0 = bias[bofs + col], b1 = bias[bofs + col + 1];
            int r0 = n0 + wm + mt * 16 + qr;
            size_t g0 = (size_t)r0 * 768 + wr0 + col;
            size_t g1 = (size_t)(r0 + 8) * 768 + wr0 + col;
            *(float2*)&g_g[g0] = make_float2(c[mt][nt][0] + b0, c[mt][nt][1] + b1);
            *(float2*)&g_g[g1] = make_float2(c[mt][nt][2] + b0, c[mt][nt][3] + b1);
        }
    }
}

// =================================================================================
// Kernel D: GRU elementwise + BN column-stat accumulation.
// =================================================================================
__global__ __launch_bounds__(256) void gru_kernel(const float* __restrict__ x)
{
    __shared__ float rs_[8][128];
    __shared__ float rq_[8][128];

    const int tid = threadIdx.x;
    const int c4 = tid & 31;
    const int rs = tid >> 5;
    float4 s = make_float4(0.f, 0.f, 0.f, 0.f);
    float4 q = make_float4(0.f, 0.f, 0.f, 0.f);

    for (int it = 0; it < 16; it++) {
        int n = blockIdx.x * 128 + it * 8 + rs;
        if (n >= N_NODES) break;
        size_t gb = (size_t)n * 768 + c4 * 4;
        float4 ir = *(const float4*)&g_g[gb];
        float4 iz = *(const float4*)&g_g[gb + 128];
        float4 in_ = *(const float4*)&g_g[gb + 256];
        float4 hr = *(const float4*)&g_g[gb + 384];
        float4 hz = *(const float4*)&g_g[gb + 512];
        float4 hn = *(const float4*)&g_g[gb + 640];
        float4 xv = *(const float4*)&x[(size_t)n * D + c4 * 4];

        float4 h;
        {
            float r = sigm(ir.x + hr.x), z = sigm(iz.x + hz.x);
            float nn = tanhf(in_.x + r * hn.x); h.x = (1.f - z) * nn + z * xv.x;
        }
        {
            float r = sigm(ir.y + hr.y), z = sigm(iz.y + hz.y);
            float nn = tanhf(in_.y + r * hn.y); h.y = (1.f - z) * nn + z * xv.y;
        }
        {
            float r = sigm(ir.z + hr.z), z = sigm(iz.z + hz.z);
            float nn = tanhf(in_.z + r * hn.z); h.z = (1.f - z) * nn + z * xv.z;
        }
        {
            float r = sigm(ir.w + hr.w), z = sigm(iz.w + hz.w);
            float nn = tanhf(in_.w + r * hn.w); h.w = (1.f - z) * nn + z * xv.w;
        }
        *(float4*)&g_h[(size_t)n * D + c4 * 4] = h;
        s.x += h.x; s.y += h.y; s.z += h.z; s.w += h.w;
        q.x += h.x * h.x; q.y += h.y * h.y; q.z += h.z * h.z; q.w += h.w * h.w;
    }

    *(float4*)&rs_[rs][c4 * 4] = s;
    *(float4*)&rq_[rs][c4 * 4] = q;
    __syncthreads();
    if (tid < 128) {
        float a = 0.f, b = 0.f;
#pragma unroll
        for (int r = 0; r < 8; r++) { a += rs_[r][tid]; b += rq_[r][tid]; }
        atomicAdd(&g_sum[tid], a);
        atomicAdd(&g_ssq[tid], b);
    }
}

// =================================================================================
// Kernel E: BatchNorm normalize.
// =================================================================================
__global__ __launch_bounds__(256) void bn_kernel(
    const float* __restrict__ gamma, const float* __restrict__ beta,
    float* __restrict__ out)
{
    int idx = blockIdx.x * 256 + threadIdx.x;
    if (idx >= N_NODES * 32) return;
    int c4 = idx & 31;
    const float inv_n = 1.f / (float)N_NODES;

    float4 h  = *(const float4*)&g_h[(size_t)idx * 4];
    float4 sm = *(const float4*)&g_sum[c4 * 4];
    float4 sq = *(const float4*)&g_ssq[c4 * 4];
    float4 ga = *(const float4*)&gamma[c4 * 4];
    float4 be = *(const float4*)&beta[c4 * 4];

    float4 o;
    {
        float mean = sm.x * inv_n; float var = sq.x * inv_n - mean * mean;
        o.x = ga.x * (h.x - mean) * rsqrtf(var + BN_EPS) + be.x;
    }
    {
        float mean = sm.y * inv_n; float var = sq.y * inv_n - mean * mean;
        o.y = ga.y * (h.y - mean) * rsqrtf(var + BN_EPS) + be.y;
    }
    {
        float mean = sm.z * inv_n; float var = sq.z * inv_n - mean * mean;
        o.z = ga.z * (h.z - mean) * rsqrtf(var + BN_EPS) + be.z;
    }
    {
        float mean = sm.w * inv_n; float var = sq.w * inv_n - mean * mean;
        o.w = ga.w * (h.w - mean) * rsqrtf(var + BN_EPS) + be.w;
    }
    *(float4*)&out[(size_t)idx * 4] = o;
}

// =================================================================================
extern "C" void kernel_launch(void* const* d_in, const int* in_sizes, int n_in,
                              void* d_out, int out_size)
{
    const float* x     = (const float*)d_in[0];
    const void*  ei    = d_in[1];
    const float* W_msg = (const float*)d_in[2];
    const float* b_msg = (const float*)d_in[3];
    const float* W_att = (const float*)d_in[4];
    const float* b_att = (const float*)d_in[5];
    const float* W_ih  = (const float*)d_in[6];
    const float* b_ih  = (const float*)d_in[7];
    const float* W_hh  = (const float*)d_in[8];
    const float* b_hh  = (const float*)d_in[9];
    const float* gamma = (const float*)d_in[10];
    const float* beta  = (const float*)d_in[11];
    float* out = (float*)d_out;

    const int E = in_sizes[1] / 2;

    static int smem_set = 0;
    if (!smem_set) {
        cudaFuncSetAttribute(gemm_mma_kernel,
                             cudaFuncAttributeMaxDynamicSharedMemorySize, SMEM_GEMM);
        smem_set = 1;
    }

    detect_kernel<<<1, 1>>>(ei, E);
    node_pre_kernel<<<NP / 64, 256>>>(x, W_msg, b_msg, W_att);
    hist_kernel<<<(E + 255) / 256, 256>>>(ei, E);
    scan_a_kernel<<<NSCAN / 256, 256>>>();
    scan_b_kernel<<<1, 256>>>();
    scan_c_kernel<<<NSCAN / 256, 256>>>();
    scatter_kernel<<<(E + 255) / 256, 256>>>(ei, E);
    gather_kernel<<<(NP + 7) / 8, 256>>>(b_att);
    convert_kernel<<<(CVT_AGG_Q + CVT_W_Q + 255) / 256, 256>>>(W_ih, W_hh);
    gemm_mma_kernel<<<dim3(12, NP / 128), 256, SMEM_GEMM>>>(b_ih, b_hh);
    gru_kernel<<<NP / 128, 256>>>(x);
    bn_kernel<<<(N_NODES * 32 + 255) / 256, 256>>>(gamma, beta, out);
}

// round 7
// speedup vs baseline: 1.8292x; 1.2028x over previous
#include <cuda_runtime.h>
#include <cuda_bf16.h>
#include <cstdint>
#include <cstddef>

// Problem constants
#define N_NODES 50000
#define NP      50048          // padded: 782*64 = 391*128
#define NSCAN   50176          // NP + 128, = 196*256 for scan
#define D       128
#define E_MAX   800000
#define BN_EPS  1e-5f

// ---------------- scratch (static device globals; no runtime alloc) -------------
__device__ float g_x  [(size_t)NP * D];
__device__ float g_m  [(size_t)NP * D];
__device__ float g_as [NP];
__device__ float g_ad [NP];
__device__ float g_g  [(size_t)NP * 768];
__device__ float g_h  [(size_t)NP * D];
__device__ float g_sum[D];
__device__ float g_ssq[D];
__device__ int   g_is64;

// CSR build for edge gather
__device__ int g_cnt [NSCAN];
__device__ int g_off [NSCAN];
__device__ int g_bsum[256];
__device__ int g_boff[256];
__device__ int g_start[NSCAN];
__device__ int g_cur [NSCAN];
__device__ int g_esrc[E_MAX];

// bf16 hi/lo planes for tensor-core GEMMs
__device__ __nv_bfloat16 g_xh  [(size_t)NP * D];
__device__ __nv_bfloat16 g_xl  [(size_t)NP * D];
__device__ __nv_bfloat16 g_agh [(size_t)NP * D];
__device__ __nv_bfloat16 g_agl [(size_t)NP * D];
__device__ __nv_bfloat16 g_wh  [896 * D];   // [W_ih(384); W_hh(384); W_msg^T(128)] hi
__device__ __nv_bfloat16 g_wl  [896 * D];   // lo

__device__ __forceinline__ float sigm(float v) { return 1.f / (1.f + __expf(-v)); }

__device__ __forceinline__ uint32_t smem_u32(const void* p) {
    uint32_t a;
    asm("{ .reg .u64 t; cvta.to.shared.u64 t, %1; cvt.u32.u64 %0, t; }" : "=r"(a) : "l"(p));
    return a;
}
__device__ __forceinline__ void f2bf(float v, __nv_bfloat16& h, __nv_bfloat16& l) {
    h = __float2bfloat16(v);
    l = __float2bfloat16(v - __bfloat162float(h));
}

// =================================================================================
// Kernel 0: detect edge_index dtype (int32 vs int64).
// =================================================================================
__global__ void detect_kernel(const void* ei_raw, int E)
{
    const long long* e64 = (const long long*)ei_raw;
    int n = E < 64 ? E : 64;
    int ok = 1;
    for (int i = 0; i < n; i++) {
        long long v = e64[i];
        if (v < 0 || v >= N_NODES) { ok = 0; break; }
    }
    g_is64 = ok;
}

__device__ __forceinline__ void load_edge(const void* ei_raw, int E, int e,
                                          int& src, int& dst)
{
    if (g_is64) {
        const long long* p = (const long long*)ei_raw;
        src = (int)p[e];
        dst = (int)p[(size_t)E + e];
    } else {
        const int* p = (const int*)ei_raw;
        src = p[e];
        dst = p[E + e];
    }
}

// =================================================================================
// Kernel A: x copy + bf16 planes + attention pre-dots + counter/accumulator zeroing.
// (m = x@W_msg+b moved to the tensor-core path.)
// =================================================================================
__global__ __launch_bounds__(256) void node_pre_kernel(
    const float* __restrict__ x, const float* __restrict__ W_att)
{
    __shared__ __align__(16) float xs[64][132];
    __shared__ float Was[128], Wad[128];

    const int tid = threadIdx.x;
    const int n0  = blockIdx.x * 64;

    if (tid < 128) { Was[tid] = W_att[tid]; Wad[tid] = W_att[128 + tid]; }
    if (tid < 64) g_cnt[n0 + tid] = 0;
    if (blockIdx.x == 0 && tid < 128) {
        g_sum[tid] = 0.f; g_ssq[tid] = 0.f; g_cnt[NP + tid] = 0;
    }

    for (int i = tid; i < 64 * 32; i += 256) {
        int node = i >> 5, cq = i & 31;
        float4 v = make_float4(0.f, 0.f, 0.f, 0.f);
        int gn = n0 + node;
        if (gn < N_NODES) v = *(const float4*)&x[(size_t)gn * D + cq * 4];
        *(float4*)&xs[node][cq * 4] = v;
        *(float4*)&g_x[(size_t)gn * D + cq * 4] = v;
        __nv_bfloat162 h01, h23, l01, l23;
        f2bf(v.x, h01.x, l01.x); f2bf(v.y, h01.y, l01.y);
        f2bf(v.z, h23.x, l23.x); f2bf(v.w, h23.y, l23.y);
        *(__nv_bfloat162*)&g_xh[(size_t)gn * D + cq * 4]     = h01;
        *(__nv_bfloat162*)&g_xh[(size_t)gn * D + cq * 4 + 2] = h23;
        *(__nv_bfloat162*)&g_xl[(size_t)gn * D + cq * 4]     = l01;
        *(__nv_bfloat162*)&g_xl[(size_t)gn * D + cq * 4 + 2] = l23;
    }
    __syncthreads();

    if (tid < 128) {
        int node = tid >> 1, sel = tid & 1;
        const float* wv = sel ? Wad : Was;
        float a0 = 0.f, a1 = 0.f, a2 = 0.f, a3 = 0.f;
#pragma unroll 8
        for (int k = 0; k < 128; k += 4) {
            a0 += xs[node][k]     * wv[k];
            a1 += xs[node][k + 1] * wv[k + 1];
            a2 += xs[node][k + 2] * wv[k + 2];
            a3 += xs[node][k + 3] * wv[k + 3];
        }
        float r = (a0 + a1) + (a2 + a3);
        if (sel) g_ad[n0 + node] = r; else g_as[n0 + node] = r;
    }
}

// =================================================================================
// Convert weights -> stacked bf16 hi/lo planes.
// Rows 0..383: W_ih; 384..767: W_hh; 768..895: W_msg^T.
// =================================================================================
#define CVT_W_Q (896 * 32)
__global__ __launch_bounds__(256) void convert_w_kernel(
    const float* __restrict__ W_ih, const float* __restrict__ W_hh,
    const float* __restrict__ W_msg)
{
    int idx = blockIdx.x * 256 + threadIdx.x;
    if (idx >= CVT_W_Q) return;
    int row = idx >> 5, cq = idx & 31;
    size_t off = (size_t)row * D + cq * 4;

    float4 v;
    if (row < 384) {
        v = *(const float4*)&W_ih[(size_t)row * D + cq * 4];
    } else if (row < 768) {
        v = *(const float4*)&W_hh[(size_t)(row - 384) * D + cq * 4];
    } else {
        int j = row - 768;                     // output col of W_msg
        int k = cq * 4;                        // input k
        v.x = W_msg[(size_t)(k + 0) * D + j];
        v.y = W_msg[(size_t)(k + 1) * D + j];
        v.z = W_msg[(size_t)(k + 2) * D + j];
        v.w = W_msg[(size_t)(k + 3) * D + j];
    }
    __nv_bfloat162 h01, h23, l01, l23;
    f2bf(v.x, h01.x, l01.x); f2bf(v.y, h01.y, l01.y);
    f2bf(v.z, h23.x, l23.x); f2bf(v.w, h23.y, l23.y);
    *(__nv_bfloat162*)&g_wh[off]     = h01;
    *(__nv_bfloat162*)&g_wh[off + 2] = h23;
    *(__nv_bfloat162*)&g_wl[off]     = l01;
    *(__nv_bfloat162*)&g_wl[off + 2] = l23;
}

// =================================================================================
// CSR build: histogram -> scan (3 kernels) -> scatter.
// =================================================================================
__global__ __launch_bounds__(256) void hist_kernel(const void* __restrict__ ei, int E)
{
    int e = blockIdx.x * 256 + threadIdx.x;
    if (e >= E) return;
    int src, dst;
    load_edge(ei, E, e, src, dst);
    if ((unsigned)dst >= N_NODES) return;
    atomicAdd(&g_cnt[dst], 1);
}

__global__ __launch_bounds__(256) void scan_a_kernel()
{
    __shared__ int sh[256];
    const int tid = threadIdx.x;
    int t = blockIdx.x * 256 + tid;
    int v = g_cnt[t];
    sh[tid] = v; __syncthreads();
#pragma unroll
    for (int o = 1; o < 256; o <<= 1) {
        int u = (tid >= o) ? sh[tid - o] : 0;
        __syncthreads();
        sh[tid] += u;
        __syncthreads();
    }
    g_off[t] = sh[tid] - v;
    if (tid == 255) g_bsum[blockIdx.x] = sh[255];
}

__global__ __launch_bounds__(256) void scan_b_kernel()
{
    __shared__ int sh[256];
    const int tid = threadIdx.x;
    int v = (tid < NSCAN / 256) ? g_bsum[tid] : 0;
    sh[tid] = v; __syncthreads();
#pragma unroll
    for (int o = 1; o < 256; o <<= 1) {
        int u = (tid >= o) ? sh[tid - o] : 0;
        __syncthreads();
        sh[tid] += u;
        __syncthreads();
    }
    g_boff[tid] = sh[tid] - v;
}

__global__ __launch_bounds__(256) void scan_c_kernel()
{
    int t = blockIdx.x * 256 + threadIdx.x;
    int s = g_off[t] + g_boff[blockIdx.x];
    g_start[t] = s;
    g_cur[t]   = s;
}

__global__ __launch_bounds__(256) void scatter_kernel(const void* __restrict__ ei, int E)
{
    int e = blockIdx.x * 256 + threadIdx.x;
    if (e >= E) return;
    int src, dst;
    load_edge(ei, E, e, src, dst);
    if ((unsigned)src >= N_NODES || (unsigned)dst >= N_NODES) return;
    int p = atomicAdd(&g_cur[dst], 1);
    if (p < E) g_esrc[p] = src;
}

// =================================================================================
// Gather: one warp per dst node; writes agg directly as bf16 hi/lo planes.
// =================================================================================
__global__ __launch_bounds__(256) void gather_kernel(const float* __restrict__ b_att)
{
    const int wid  = threadIdx.x >> 5;
    const int lane = threadIdx.x & 31;
    const int n = blockIdx.x * 8 + wid;
    if (n >= NP) return;

    const int s0 = g_start[n];
    const int s1 = g_start[n + 1];
    const float adb = ((n < N_NODES) ? g_ad[n] : 0.f) + b_att[0];

    float4 acc = make_float4(0.f, 0.f, 0.f, 0.f);
    int i = s0;
    for (; i + 1 < s1; i += 2) {
        int src0 = g_esrc[i], src1 = g_esrc[i + 1];
        float at0 = sigm(g_as[src0] + adb);
        float at1 = sigm(g_as[src1] + adb);
        float4 v0 = *(const float4*)&g_m[(size_t)src0 * D + lane * 4];
        float4 v1 = *(const float4*)&g_m[(size_t)src1 * D + lane * 4];
        acc.x += v0.x * at0 + v1.x * at1;
        acc.y += v0.y * at0 + v1.y * at1;
        acc.z += v0.z * at0 + v1.z * at1;
        acc.w += v0.w * at0 + v1.w * at1;
    }
    if (i < s1) {
        int src0 = g_esrc[i];
        float at0 = sigm(g_as[src0] + adb);
        float4 v0 = *(const float4*)&g_m[(size_t)src0 * D + lane * 4];
        acc.x += v0.x * at0; acc.y += v0.y * at0;
        acc.z += v0.z * at0; acc.w += v0.w * at0;
    }
    __nv_bfloat162 h01, h23, l01, l23;
    f2bf(acc.x, h01.x, l01.x); f2bf(acc.y, h01.y, l01.y);
    f2bf(acc.z, h23.x, l23.x); f2bf(acc.w, h23.y, l23.y);
    size_t o = (size_t)n * D + lane * 4;
    *(__nv_bfloat162*)&g_agh[o]     = h01;
    *(__nv_bfloat162*)&g_agh[o + 2] = h23;
    *(__nv_bfloat162*)&g_agl[o]     = l01;
    *(__nv_bfloat162*)&g_agl[o + 2] = l23;
}

// =================================================================================
// Split-bf16 GEMM core via mma.sync + ldmatrix. 128 nodes x 128 cols per block.
// 8 warps 4(M) x 2(N); warp tile 32x64 = 2x8 m16n8k16 tiles.
// 3 passes: Ah*Bh + Al*Bh + Ah*Bl, fp32 accum.
// =================================================================================
#define AS_STR 264
#define SMEM_GEMM (2 * 128 * AS_STR * 2)

__device__ __forceinline__ void mma16816(float* c, const uint32_t* a, const uint32_t* b) {
    asm volatile(
        "mma.sync.aligned.m16n8k16.row.col.f32.bf16.bf16.f32 "
        "{%0,%1,%2,%3}, {%4,%5,%6,%7}, {%8,%9}, {%0,%1,%2,%3};"
        : "+f"(c[0]), "+f"(c[1]), "+f"(c[2]), "+f"(c[3])
        : "r"(a[0]), "r"(a[1]), "r"(a[2]), "r"(a[3]), "r"(b[0]), "r"(b[1]));
}
__device__ __forceinline__ void ldmx4(uint32_t* d, uint32_t addr) {
    asm volatile("ldmatrix.sync.aligned.m8n8.x4.shared.b16 {%0,%1,%2,%3}, [%4];"
                 : "=r"(d[0]), "=r"(d[1]), "=r"(d[2]), "=r"(d[3]) : "r"(addr));
}

__device__ __forceinline__ void gemm_core(
    const __nv_bfloat16* __restrict__ Ah, const __nv_bfloat16* __restrict__ Al,
    int brow0, const float* __restrict__ bias, float* __restrict__ out,
    int ostride, int ocol0, int n0, __nv_bfloat16* smem)
{
    __nv_bfloat16* sA = smem;                    // [128][AS_STR]
    __nv_bfloat16* sB = smem + 128 * AS_STR;     // [128][AS_STR]
    const int tid = threadIdx.x;

#pragma unroll
    for (int it = 0; it < 8; it++) {
        int i = tid + it * 256;                  // 2048 chunks of 8 bf16
        int row = i >> 4, col = (i & 15) * 8;
        size_t ga = (size_t)(n0 + row) * D + col;
        size_t gb = (size_t)(brow0 + row) * D + col;
        *(uint4*)&sA[row * AS_STR + col]       = *(const uint4*)&Ah[ga];
        *(uint4*)&sA[row * AS_STR + 128 + col] = *(const uint4*)&Al[ga];
        *(uint4*)&sB[row * AS_STR + col]       = *(const uint4*)&g_wh[gb];
        *(uint4*)&sB[row * AS_STR + 128 + col] = *(const uint4*)&g_wl[gb];
    }
    __syncthreads();

    const int wid  = tid >> 5;
    const int lane = tid & 31;
    const int wm = (wid & 3) * 32;
    const int wn = (wid >> 2) * 64;
    const int g  = lane >> 3;
    const int r  = lane & 7;
    const int qr = lane >> 2;
    const int qc = (lane & 3) * 2;

    uint32_t aBase[2], bBase[4];
#pragma unroll
    for (int mt = 0; mt < 2; mt++) {
        int row = wm + mt * 16 + ((g & 1) ? 8 : 0) + r;
        int col = (g >= 2) ? 8 : 0;
        aBase[mt] = smem_u32(&sA[row * AS_STR + col]);
    }
#pragma unroll
    for (int ntp = 0; ntp < 4; ntp++) {
        int row = wn + (ntp * 2 + (g >> 1)) * 8 + r;
        int col = (g & 1) ? 8 : 0;
        bBase[ntp] = smem_u32(&sB[row * AS_STR + col]);
    }

    float c[2][8][4];
#pragma unroll
    for (int mt = 0; mt < 2; mt++)
#pragma unroll
        for (int nt = 0; nt < 8; nt++)
#pragma unroll
            for (int j = 0; j < 4; j++) c[mt][nt][j] = 0.f;

#pragma unroll
    for (int pass = 0; pass < 3; pass++) {
        const int kA = (pass == 1) ? 128 : 0;
        const int kB = (pass == 2) ? 128 : 0;
#pragma unroll
        for (int s = 0; s < 8; s++) {
            const uint32_t offA = (uint32_t)((kA + s * 16) * 2);
            const uint32_t offB = (uint32_t)((kB + s * 16) * 2);
            uint32_t a[2][4], b[4][4];
            ldmx4(a[0], aBase[0] + offA);
            ldmx4(a[1], aBase[1] + offA);
#pragma unroll
            for (int ntp = 0; ntp < 4; ntp++) ldmx4(b[ntp], bBase[ntp] + offB);
#pragma unroll
            for (int mt = 0; mt < 2; mt++)
#pragma unroll
                for (int ntp = 0; ntp < 4; ntp++) {
                    mma16816(c[mt][ntp * 2],     a[mt], &b[ntp][0]);
                    mma16816(c[mt][ntp * 2 + 1], a[mt], &b[ntp][2]);
                }
        }
    }

#pragma unroll
    for (int mt = 0; mt < 2; mt++) {
#pragma unroll
        for (int nt = 0; nt < 8; nt++) {
            int col = wn + nt * 8 + qc;
            float b0 = bias[col], b1 = bias[col + 1];
            int r0 = n0 + wm + mt * 16 + qr;
            size_t g0 = (size_t)r0 * ostride + ocol0 + col;
            size_t g1 = (size_t)(r0 + 8) * ostride + ocol0 + col;
            *(float2*)&out[g0] = make_float2(c[mt][nt][0] + b0, c[mt][nt][1] + b1);
            *(float2*)&out[g1] = make_float2(c[mt][nt][2] + b0, c[mt][nt][3] + b1);
        }
    }
}

__global__ __launch_bounds__(256) void gemm_main_kernel(
    const float* __restrict__ b_ih, const float* __restrict__ b_hh)
{
    extern __shared__ __align__(16) __nv_bfloat16 smem[];
    const int bx = blockIdx.x;
    const bool ih = (bx < 3);
    gemm_core(ih ? g_agh : g_xh, ih ? g_agl : g_xl,
              bx * 128,
              ih ? (b_ih + bx * 128) : (b_hh + (bx - 3) * 128),
              g_g, 768, bx * 128, blockIdx.y * 128, smem);
}

__global__ __launch_bounds__(256) void gemm_msg_kernel(const float* __restrict__ b_msg)
{
    extern __shared__ __align__(16) __nv_bfloat16 smem[];
    gemm_core(g_xh, g_xl, 768, b_msg, g_m, 128, 0, blockIdx.x * 128, smem);
}

// =================================================================================
// Kernel D: GRU elementwise + BN column-stat accumulation.
// =================================================================================
__global__ __launch_bounds__(256) void gru_kernel(const float* __restrict__ x)
{
    __shared__ float rs_[8][128];
    __shared__ float rq_[8][128];

    const int tid = threadIdx.x;
    const int c4 = tid & 31;
    const int rs = tid >> 5;
    float4 s = make_float4(0.f, 0.f, 0.f, 0.f);
    float4 q = make_float4(0.f, 0.f, 0.f, 0.f);

    for (int it = 0; it < 16; it++) {
        int n = blockIdx.x * 128 + it * 8 + rs;
        if (n >= N_NODES) break;
        size_t gb = (size_t)n * 768 + c4 * 4;
        float4 ir = *(const float4*)&g_g[gb];
        float4 iz = *(const float4*)&g_g[gb + 128];
        float4 in_ = *(const float4*)&g_g[gb + 256];
        float4 hr = *(const float4*)&g_g[gb + 384];
        float4 hz = *(const float4*)&g_g[gb + 512];
        float4 hn = *(const float4*)&g_g[gb + 640];
        float4 xv = *(const float4*)&x[(size_t)n * D + c4 * 4];

        float4 h;
        {
            float r = sigm(ir.x + hr.x), z = sigm(iz.x + hz.x);
            float nn = tanhf(in_.x + r * hn.x); h.x = (1.f - z) * nn + z * xv.x;
        }
        {
            float r = sigm(ir.y + hr.y), z = sigm(iz.y + hz.y);
            float nn = tanhf(in_.y + r * hn.y); h.y = (1.f - z) * nn + z * xv.y;
        }
        {
            float r = sigm(ir.z + hr.z), z = sigm(iz.z + hz.z);
            float nn = tanhf(in_.z + r * hn.z); h.z = (1.f - z) * nn + z * xv.z;
        }
        {
            float r = sigm(ir.w + hr.w), z = sigm(iz.w + hz.w);
            float nn = tanhf(in_.w + r * hn.w); h.w = (1.f - z) * nn + z * xv.w;
        }
        *(float4*)&g_h[(size_t)n * D + c4 * 4] = h;
        s.x += h.x; s.y += h.y; s.z += h.z; s.w += h.w;
        q.x += h.x * h.x; q.y += h.y * h.y; q.z += h.z * h.z; q.w += h.w * h.w;
    }

    *(float4*)&rs_[rs][c4 * 4] = s;
    *(float4*)&rq_[rs][c4 * 4] = q;
    __syncthreads();
    if (tid < 128) {
        float a = 0.f, b = 0.f;
#pragma unroll
        for (int r = 0; r < 8; r++) { a += rs_[r][tid]; b += rq_[r][tid]; }
        atomicAdd(&g_sum[tid], a);
        atomicAdd(&g_ssq[tid], b);
    }
}

// =================================================================================
// Kernel E: BatchNorm normalize.
// =================================================================================
__global__ __launch_bounds__(256) void bn_kernel(
    const float* __restrict__ gamma, const float* __restrict__ beta,
    float* __restrict__ out)
{
    int idx = blockIdx.x * 256 + threadIdx.x;
    if (idx >= N_NODES * 32) return;
    int c4 = idx & 31;
    const float inv_n = 1.f / (float)N_NODES;

    float4 h  = *(const float4*)&g_h[(size_t)idx * 4];
    float4 sm = *(const float4*)&g_sum[c4 * 4];
    float4 sq = *(const float4*)&g_ssq[c4 * 4];
    float4 ga = *(const float4*)&gamma[c4 * 4];
    float4 be = *(const float4*)&beta[c4 * 4];

    float4 o;
    {
        float mean = sm.x * inv_n; float var = sq.x * inv_n - mean * mean;
        o.x = ga.x * (h.x - mean) * rsqrtf(var + BN_EPS) + be.x;
    }
    {
        float mean = sm.y * inv_n; float var = sq.y * inv_n - mean * mean;
        o.y = ga.y * (h.y - mean) * rsqrtf(var + BN_EPS) + be.y;
    }
    {
        float mean = sm.z * inv_n; float var = sq.z * inv_n - mean * mean;
        o.z = ga.z * (h.z - mean) * rsqrtf(var + BN_EPS) + be.z;
    }
    {
        float mean = sm.w * inv_n; float var = sq.w * inv_n - mean * mean;
        o.w = ga.w * (h.w - mean) * rsqrtf(var + BN_EPS) + be.w;
    }
    *(float4*)&out[(size_t)idx * 4] = o;
}

// =================================================================================
extern "C" void kernel_launch(void* const* d_in, const int* in_sizes, int n_in,
                              void* d_out, int out_size)
{
    const float* x     = (const float*)d_in[0];
    const void*  ei    = d_in[1];
    const float* W_msg = (const float*)d_in[2];
    const float* b_msg = (const float*)d_in[3];
    const float* W_att = (const float*)d_in[4];
    const float* b_att = (const float*)d_in[5];
    const float* W_ih  = (const float*)d_in[6];
    const float* b_ih  = (const float*)d_in[7];
    const float* W_hh  = (const float*)d_in[8];
    const float* b_hh  = (const float*)d_in[9];
    const float* gamma = (const float*)d_in[10];
    const float* beta  = (const float*)d_in[11];
    float* out = (float*)d_out;

    const int E = in_sizes[1] / 2;

    static int smem_set = 0;
    if (!smem_set) {
        cudaFuncSetAttribute(gemm_main_kernel,
                             cudaFuncAttributeMaxDynamicSharedMemorySize, SMEM_GEMM);
        cudaFuncSetAttribute(gemm_msg_kernel,
                             cudaFuncAttributeMaxDynamicSharedMemorySize, SMEM_GEMM);
        smem_set = 1;
    }

    detect_kernel<<<1, 1>>>(ei, E);
    node_pre_kernel<<<NP / 64, 256>>>(x, W_att);
    convert_w_kernel<<<(CVT_W_Q + 255) / 256, 256>>>(W_ih, W_hh, W_msg);
    gemm_msg_kernel<<<NP / 128, 256, SMEM_GEMM>>>(b_msg);
    hist_kernel<<<(E + 255) / 256, 256>>>(ei, E);
    scan_a_kernel<<<NSCAN / 256, 256>>>();
    scan_b_kernel<<<1, 256>>>();
    scan_c_kernel<<<NSCAN / 256, 256>>>();
    scatter_kernel<<<(E + 255) / 256, 256>>>(ei, E);
    gather_kernel<<<(NP + 7) / 8, 256>>>(b_att);
    gemm_main_kernel<<<dim3(6, NP / 128), 256, SMEM_GEMM>>>(b_ih, b_hh);
    gru_kernel<<<NP / 128, 256>>>(x);
    bn_kernel<<<(N_NODES * 32 + 255) / 256, 256>>>(gamma, beta, out);
}